// round 4
// baseline (speedup 1.0000x reference)
#include <cuda_runtime.h>

// ---------------------------------------------------------------------------
// DeeperGCN round 3:
//  - round-2 design, with GEMM smem moved to dynamic shared memory (the 48KB
//    static cap caused the ptxas failure; opt-in dynamic goes to 227KB)
//  - smem-tiled register-blocked SGEMMs, fused LN/ReLU/head epilogues
//  - aggregation: eps folded out of inner loop, degree-4 exp2
// ---------------------------------------------------------------------------

#define NMAX 50048
#define EMAX 800000

__device__ int   g_is64;
__device__ int   g_src[EMAX];
__device__ int   g_dst[EMAX];
__device__ int   g_ssrc[EMAX];
__device__ int   g_deg[NMAX];
__device__ int   g_off[NMAX];
__device__ int   g_cur[NMAX];
__device__ float g_h  [NMAX * 64];
__device__ float g_z  [NMAX * 64];
__device__ float g_s  [NMAX * 64];
__device__ float g_hid[NMAX * 128];

// fast exp2 on FMA pipe, degree-4, rel err ~4e-5
__device__ __forceinline__ float fast_exp2(float x) {
    const float C = 12582912.0f;               // 1.5 * 2^23
    float fb = x + C;
    float r  = x - (fb - C);
    float p  = 9.6181291976956636e-3f;
    p = fmaf(p, r, 5.5504108664821580e-2f);
    p = fmaf(p, r, 2.4022650695910072e-1f);
    p = fmaf(p, r, 6.9314718055994531e-1f);
    p = fmaf(p, r, 1.0f);
    return __int_as_float(__float_as_int(p) + (__float_as_int(fb) << 23));
}

// ---------------------------------------------------------------------------
// Edge preprocessing
// ---------------------------------------------------------------------------
__global__ void k_detect(const int* __restrict__ w, int E) {
    int lane = threadIdx.x;
    int bad = 0;
    int lim = min(128, E);
    for (int i = lane; i < lim; i += 32) bad |= w[2 * i + 1];
    unsigned b = __ballot_sync(0xffffffffu, bad != 0);
    if (lane == 0) g_is64 = (b == 0) ? 1 : 0;
}

__global__ void k_normcount(const void* __restrict__ raw, int E) {
    int e = blockIdx.x * blockDim.x + threadIdx.x;
    if (e >= E) return;
    int s, d;
    if (g_is64) {
        const long long* p = (const long long*)raw;
        s = (int)p[e]; d = (int)p[(size_t)E + e];
    } else {
        const int* p = (const int*)raw;
        s = p[e]; d = p[(size_t)E + e];
    }
    g_src[e] = s; g_dst[e] = d;
    atomicAdd(&g_deg[d], 1);
}

__global__ void k_scan(int n) {
    __shared__ int sm[1024];
    int t = threadIdx.x;
    int IT = (n + 1023) >> 10;
    int base = t * IT;
    int s = 0;
    for (int i = 0; i < IT; i++) { int id = base + i; if (id < n) s += g_deg[id]; }
    sm[t] = s;
    __syncthreads();
    for (int off = 1; off < 1024; off <<= 1) {
        int v = (t >= off) ? sm[t - off] : 0;
        __syncthreads();
        sm[t] += v;
        __syncthreads();
    }
    int pre = (t == 0) ? 0 : sm[t - 1];
    for (int i = 0; i < IT; i++) {
        int id = base + i;
        if (id < n) { g_off[id] = pre; g_cur[id] = pre; pre += g_deg[id]; }
    }
}

__global__ void k_scatter(int E) {
    int e = blockIdx.x * blockDim.x + threadIdx.x;
    if (e >= E) return;
    int d = g_dst[e];
    int pos = atomicAdd(&g_cur[d], 1);
    g_ssrc[pos] = g_src[e];
}

// ---------------------------------------------------------------------------
// Softmax aggregation, warp per destination node (eps folded into epilogue)
// ---------------------------------------------------------------------------
__global__ void k_aggr(const float* __restrict__ z, const float* __restrict__ tp,
                       int li, float* __restrict__ so, int N) {
    int w = (blockIdx.x * blockDim.x + threadIdx.x) >> 5;
    int lane = threadIdx.x & 31;
    if (w >= N) return;
    float tl = __ldg(tp + li) * 1.4426950408889634f;
    int beg = g_off[w], dg = g_deg[w];
    const float2* z2 = (const float2*)z;
    float se0 = 0.f, se1 = 0.f, sn0 = 0.f, sn1 = 0.f;
    #pragma unroll 2
    for (int j = 0; j < dg; j++) {
        int s = __ldg(&g_ssrc[beg + j]);
        float2 v = __ldg(&z2[(size_t)s * 32 + lane]);
        float m0 = fmaxf(v.x, 0.f);
        float m1 = fmaxf(v.y, 0.f);
        float e0 = fast_exp2(m0 * tl);
        float e1 = fast_exp2(m1 * tl);
        se0 += e0; se1 += e1;
        sn0 = fmaf(m0, e0, sn0);
        sn1 = fmaf(m1, e1, sn1);
    }
    float2 zd = __ldg(&z2[(size_t)w * 32 + lane]);
    float2 o;
    o.x = zd.x + fmaf(1e-7f, se0, sn0) / (se0 + 1e-16f);
    o.y = zd.y + fmaf(1e-7f, se1, sn1) / (se1 + 1e-16f);
    ((float2*)so)[(size_t)w * 32 + lane] = o;
}

// ---------------------------------------------------------------------------
// mlp1: [N,64] @ [64,128] + bias -> LN(128) -> ReLU
// dyn smem: As[64*64] Ws[64*128] bs/gsm/bbm[128]
// 256 threads (16x16), 4 rows x 8 cols per thread
// ---------------------------------------------------------------------------
#define MLP1_SMEM ((64 * 64 + 64 * 128 + 3 * 128) * 4)
__global__ __launch_bounds__(256) void k_mlp1(
    const float* __restrict__ A, const float* __restrict__ W,
    const float* __restrict__ bias, const float* __restrict__ lg,
    const float* __restrict__ lb, float* __restrict__ out, int N) {
    extern __shared__ float sm[];
    float* As  = sm;                  // 4096
    float* Ws  = sm + 4096;           // 8192
    float* bs  = sm + 4096 + 8192;    // 128
    float* gsm = bs + 128;
    float* bbm = gsm + 128;
    int tid = threadIdx.x;
    {
        const float4* w4 = (const float4*)W;
        float4* s4 = (float4*)Ws;
        #pragma unroll
        for (int i = 0; i < 8; i++) s4[tid + i * 256] = w4[tid + i * 256];
        if (tid < 128) { bs[tid] = bias[tid]; gsm[tid] = lg[tid]; bbm[tid] = lb[tid]; }
    }
    int r0 = blockIdx.x * 64;
    {
        const float4* a4 = (const float4*)A;
        float4* s4 = (float4*)As;
        #pragma unroll
        for (int i = 0; i < 4; i++) {
            int idx = tid + i * 256;                 // 0..1023 (64 rows x 16 f4)
            int row = min(r0 + (idx >> 4), N - 1);
            s4[idx] = __ldg(&a4[(size_t)row * 16 + (idx & 15)]);
        }
    }
    __syncthreads();
    int tr = tid >> 4, tc = tid & 15;
    float acc[4][8];
    #pragma unroll
    for (int r = 0; r < 4; r++)
        #pragma unroll
        for (int c = 0; c < 8; c++) acc[r][c] = 0.f;
    const float4* As4 = (const float4*)As;
    const float4* Ws4 = (const float4*)Ws;
    #pragma unroll
    for (int k4 = 0; k4 < 16; k4++) {
        float4 a[4];
        #pragma unroll
        for (int r = 0; r < 4; r++) a[r] = As4[(tr * 4 + r) * 16 + k4];
        #pragma unroll
        for (int kk = 0; kk < 4; kk++) {
            float4 w0 = Ws4[(k4 * 4 + kk) * 32 + tc * 2];
            float4 w1 = Ws4[(k4 * 4 + kk) * 32 + tc * 2 + 1];
            #pragma unroll
            for (int r = 0; r < 4; r++) {
                float av = (kk == 0) ? a[r].x : (kk == 1) ? a[r].y : (kk == 2) ? a[r].z : a[r].w;
                acc[r][0] = fmaf(av, w0.x, acc[r][0]);
                acc[r][1] = fmaf(av, w0.y, acc[r][1]);
                acc[r][2] = fmaf(av, w0.z, acc[r][2]);
                acc[r][3] = fmaf(av, w0.w, acc[r][3]);
                acc[r][4] = fmaf(av, w1.x, acc[r][4]);
                acc[r][5] = fmaf(av, w1.y, acc[r][5]);
                acc[r][6] = fmaf(av, w1.z, acc[r][6]);
                acc[r][7] = fmaf(av, w1.w, acc[r][7]);
            }
        }
    }
    float4 bv0 = ((const float4*)bs)[tc * 2],  bv1 = ((const float4*)bs)[tc * 2 + 1];
    float4 gv0 = ((const float4*)gsm)[tc * 2], gv1 = ((const float4*)gsm)[tc * 2 + 1];
    float4 cv0 = ((const float4*)bbm)[tc * 2], cv1 = ((const float4*)bbm)[tc * 2 + 1];
    #pragma unroll
    for (int r = 0; r < 4; r++) {
        int rr = r0 + tr * 4 + r;
        float y[8];
        y[0] = acc[r][0] + bv0.x; y[1] = acc[r][1] + bv0.y;
        y[2] = acc[r][2] + bv0.z; y[3] = acc[r][3] + bv0.w;
        y[4] = acc[r][4] + bv1.x; y[5] = acc[r][5] + bv1.y;
        y[6] = acc[r][6] + bv1.z; y[7] = acc[r][7] + bv1.w;
        float s = 0.f, q = 0.f;
        #pragma unroll
        for (int c = 0; c < 8; c++) { s += y[c]; q = fmaf(y[c], y[c], q); }
        #pragma unroll
        for (int o = 1; o < 16; o <<= 1) {
            s += __shfl_xor_sync(0xffffffffu, s, o);
            q += __shfl_xor_sync(0xffffffffu, q, o);
        }
        float mu = s * (1.f / 128.f);
        float var = q * (1.f / 128.f) - mu * mu;
        float rs = rsqrtf(var + 1e-5f);
        float4 o0, o1;
        o0.x = fmaxf((y[0] - mu) * rs * gv0.x + cv0.x, 0.f);
        o0.y = fmaxf((y[1] - mu) * rs * gv0.y + cv0.y, 0.f);
        o0.z = fmaxf((y[2] - mu) * rs * gv0.z + cv0.z, 0.f);
        o0.w = fmaxf((y[3] - mu) * rs * gv0.w + cv0.w, 0.f);
        o1.x = fmaxf((y[4] - mu) * rs * gv1.x + cv1.x, 0.f);
        o1.y = fmaxf((y[5] - mu) * rs * gv1.y + cv1.y, 0.f);
        o1.z = fmaxf((y[6] - mu) * rs * gv1.z + cv1.z, 0.f);
        o1.w = fmaxf((y[7] - mu) * rs * gv1.w + cv1.w, 0.f);
        if (rr < N) {
            ((float4*)out)[(size_t)rr * 32 + tc * 2]     = o0;
            ((float4*)out)[(size_t)rr * 32 + tc * 2 + 1] = o1;
        }
    }
}

// ---------------------------------------------------------------------------
// gemmB: [N,128] @ [128,64] + bias  (+residual, +LN epilogue, +head)
// modes: 0 plain -> h_out; 1 -> h_out and z_out=relu(LN);
//        2 -> z_out=relu(LN) + head into z_out[N*64 ...]  (h not stored)
// dyn smem: As[64*128] Ws[128*64] bs/gsm/bbm[64] lws[208]
// 128 threads (16x8), 4 rows x 8 cols per thread
// ---------------------------------------------------------------------------
#define GEMMB_SMEM ((64 * 128 + 128 * 64 + 3 * 64 + 208) * 4)
__global__ __launch_bounds__(128) void k_gemmB(
    const float* __restrict__ A, const float* __restrict__ W,
    const float* __restrict__ bias, const float* __restrict__ lg,
    const float* __restrict__ lb, const float* __restrict__ lw,
    const float* __restrict__ lhb, float* __restrict__ h_out,
    float* __restrict__ z_out, int N, int addres, int mode) {
    extern __shared__ float sm[];
    float* As  = sm;                    // 8192
    float* Ws  = sm + 8192;             // 8192
    float* bs  = sm + 16384;            // 64
    float* gsm = bs + 64;
    float* bbm = gsm + 64;
    float* lws = bbm + 64;              // 208 (192 used, f4-aligned)
    int tid = threadIdx.x;
    {
        const float4* w4 = (const float4*)W;
        float4* s4 = (float4*)Ws;
        #pragma unroll
        for (int i = 0; i < 16; i++) s4[tid + i * 128] = w4[tid + i * 128];
        if (tid < 64) {
            bs[tid] = bias[tid];
            if (mode) { gsm[tid] = lg[tid]; bbm[tid] = lb[tid]; }
        }
        if (mode == 2 && tid < 48) ((float4*)lws)[tid] = ((const float4*)lw)[tid];
    }
    int r0 = blockIdx.x * 64;
    {
        const float4* a4 = (const float4*)A;
        float4* s4 = (float4*)As;
        #pragma unroll
        for (int i = 0; i < 16; i++) {
            int idx = tid + i * 128;                 // 0..2047 (64 rows x 32 f4)
            int row = min(r0 + (idx >> 5), N - 1);
            s4[idx] = __ldg(&a4[(size_t)row * 32 + (idx & 31)]);
        }
    }
    __syncthreads();
    int tr = tid >> 3, tc = tid & 7;
    float acc[4][8];
    #pragma unroll
    for (int r = 0; r < 4; r++)
        #pragma unroll
        for (int c = 0; c < 8; c++) acc[r][c] = 0.f;
    const float4* As4 = (const float4*)As;
    const float4* Ws4 = (const float4*)Ws;
    #pragma unroll
    for (int k4 = 0; k4 < 32; k4++) {
        float4 a[4];
        #pragma unroll
        for (int r = 0; r < 4; r++) a[r] = As4[(tr * 4 + r) * 32 + k4];
        #pragma unroll
        for (int kk = 0; kk < 4; kk++) {
            float4 w0 = Ws4[(k4 * 4 + kk) * 16 + tc * 2];
            float4 w1 = Ws4[(k4 * 4 + kk) * 16 + tc * 2 + 1];
            #pragma unroll
            for (int r = 0; r < 4; r++) {
                float av = (kk == 0) ? a[r].x : (kk == 1) ? a[r].y : (kk == 2) ? a[r].z : a[r].w;
                acc[r][0] = fmaf(av, w0.x, acc[r][0]);
                acc[r][1] = fmaf(av, w0.y, acc[r][1]);
                acc[r][2] = fmaf(av, w0.z, acc[r][2]);
                acc[r][3] = fmaf(av, w0.w, acc[r][3]);
                acc[r][4] = fmaf(av, w1.x, acc[r][4]);
                acc[r][5] = fmaf(av, w1.y, acc[r][5]);
                acc[r][6] = fmaf(av, w1.z, acc[r][6]);
                acc[r][7] = fmaf(av, w1.w, acc[r][7]);
            }
        }
    }
    float4 bv0 = ((const float4*)bs)[tc * 2], bv1 = ((const float4*)bs)[tc * 2 + 1];
    #pragma unroll
    for (int r = 0; r < 4; r++) {
        int rr = r0 + tr * 4 + r;
        bool ok = rr < N;
        float y[8];
        y[0] = acc[r][0] + bv0.x; y[1] = acc[r][1] + bv0.y;
        y[2] = acc[r][2] + bv0.z; y[3] = acc[r][3] + bv0.w;
        y[4] = acc[r][4] + bv1.x; y[5] = acc[r][5] + bv1.y;
        y[6] = acc[r][6] + bv1.z; y[7] = acc[r][7] + bv1.w;
        if (addres && ok) {
            float4 h0 = ((const float4*)h_out)[(size_t)rr * 16 + tc * 2];
            float4 h1 = ((const float4*)h_out)[(size_t)rr * 16 + tc * 2 + 1];
            y[0] += h0.x; y[1] += h0.y; y[2] += h0.z; y[3] += h0.w;
            y[4] += h1.x; y[5] += h1.y; y[6] += h1.z; y[7] += h1.w;
        }
        if (mode != 2 && ok) {
            float4 s0, s1;
            s0.x = y[0]; s0.y = y[1]; s0.z = y[2]; s0.w = y[3];
            s1.x = y[4]; s1.y = y[5]; s1.z = y[6]; s1.w = y[7];
            ((float4*)h_out)[(size_t)rr * 16 + tc * 2]     = s0;
            ((float4*)h_out)[(size_t)rr * 16 + tc * 2 + 1] = s1;
        }
        if (mode) {
            float s = 0.f, q = 0.f;
            #pragma unroll
            for (int c = 0; c < 8; c++) { s += y[c]; q = fmaf(y[c], y[c], q); }
            #pragma unroll
            for (int o = 1; o < 8; o <<= 1) {
                s += __shfl_xor_sync(0xffffffffu, s, o);
                q += __shfl_xor_sync(0xffffffffu, q, o);
            }
            float mu = s * (1.f / 64.f);
            float var = q * (1.f / 64.f) - mu * mu;
            float rs = rsqrtf(var + 1e-5f);
            float4 gv0 = ((const float4*)gsm)[tc * 2], gv1 = ((const float4*)gsm)[tc * 2 + 1];
            float4 cv0 = ((const float4*)bbm)[tc * 2], cv1 = ((const float4*)bbm)[tc * 2 + 1];
            float o8[8];
            o8[0] = fmaxf((y[0] - mu) * rs * gv0.x + cv0.x, 0.f);
            o8[1] = fmaxf((y[1] - mu) * rs * gv0.y + cv0.y, 0.f);
            o8[2] = fmaxf((y[2] - mu) * rs * gv0.z + cv0.z, 0.f);
            o8[3] = fmaxf((y[3] - mu) * rs * gv0.w + cv0.w, 0.f);
            o8[4] = fmaxf((y[4] - mu) * rs * gv1.x + cv1.x, 0.f);
            o8[5] = fmaxf((y[5] - mu) * rs * gv1.y + cv1.y, 0.f);
            o8[6] = fmaxf((y[6] - mu) * rs * gv1.z + cv1.z, 0.f);
            o8[7] = fmaxf((y[7] - mu) * rs * gv1.w + cv1.w, 0.f);
            if (ok) {
                float4 z0, z1;
                z0.x = o8[0]; z0.y = o8[1]; z0.z = o8[2]; z0.w = o8[3];
                z1.x = o8[4]; z1.y = o8[5]; z1.z = o8[6]; z1.w = o8[7];
                ((float4*)z_out)[(size_t)rr * 16 + tc * 2]     = z0;
                ((float4*)z_out)[(size_t)rr * 16 + tc * 2 + 1] = z1;
            }
            if (mode == 2) {
                float p0 = 0.f, p1 = 0.f, p2 = 0.f;
                #pragma unroll
                for (int c = 0; c < 8; c++) {
                    int col = tc * 8 + c;
                    p0 = fmaf(o8[c], lws[col * 3 + 0], p0);
                    p1 = fmaf(o8[c], lws[col * 3 + 1], p1);
                    p2 = fmaf(o8[c], lws[col * 3 + 2], p2);
                }
                #pragma unroll
                for (int o = 1; o < 8; o <<= 1) {
                    p0 += __shfl_xor_sync(0xffffffffu, p0, o);
                    p1 += __shfl_xor_sync(0xffffffffu, p1, o);
                    p2 += __shfl_xor_sync(0xffffffffu, p2, o);
                }
                if (tc == 0 && ok) {
                    size_t base = (size_t)N * 64 + (size_t)rr * 3;
                    z_out[base + 0] = p0 + __ldg(lhb + 0);
                    z_out[base + 1] = p1 + __ldg(lhb + 1);
                    z_out[base + 2] = p2 + __ldg(lhb + 2);
                }
            }
        }
    }
}

// ---------------------------------------------------------------------------
// Host launch
// ---------------------------------------------------------------------------
extern "C" void kernel_launch(void* const* d_in, const int* in_sizes, int n_in,
                              void* d_out, int out_size) {
    const float* x    = (const float*)d_in[0];
    const void*  ei   = d_in[1];
    const float* encW = (const float*)d_in[2];
    const float* encB = (const float*)d_in[3];
    const float* t    = (const float*)d_in[4];
    const float* W1   = (const float*)d_in[5];
    const float* b1   = (const float*)d_in[6];
    const float* g1   = (const float*)d_in[7];
    const float* bb1  = (const float*)d_in[8];
    const float* W2   = (const float*)d_in[9];
    const float* b2   = (const float*)d_in[10];
    const float* ng   = (const float*)d_in[11];
    const float* nb   = (const float*)d_in[12];
    const float* lw   = (const float*)d_in[13];
    const float* lb   = (const float*)d_in[14];
    int N = in_sizes[0] / 128;
    int E = in_sizes[1] / 2;
    if (N > NMAX) N = NMAX;
    if (E > EMAX) E = EMAX;
    float* out = (float*)d_out;

    cudaFuncSetAttribute(k_mlp1,  cudaFuncAttributeMaxDynamicSharedMemorySize, MLP1_SMEM);
    cudaFuncSetAttribute(k_gemmB, cudaFuncAttributeMaxDynamicSharedMemorySize, GEMMB_SMEM);

    float *gh, *gz, *gs, *ghid;
    int *gdeg;
    cudaGetSymbolAddress((void**)&gh,   g_h);
    cudaGetSymbolAddress((void**)&gz,   g_z);
    cudaGetSymbolAddress((void**)&gs,   g_s);
    cudaGetSymbolAddress((void**)&ghid, g_hid);
    cudaGetSymbolAddress((void**)&gdeg, g_deg);

    int eb = (E + 255) / 256;
    int rowsW = (N + 7) / 8;
    int tiles = (N + 63) / 64;

    // edge preprocessing (CSR by dst)
    cudaMemsetAsync(gdeg, 0, (size_t)N * sizeof(int));
    k_detect<<<1, 32>>>((const int*)ei, E);
    k_normcount<<<eb, 256>>>(ei, E);
    k_scan<<<1, 1024>>>(N);
    k_scatter<<<eb, 256>>>(E);

    // encoder: x @ encW + encB -> gh  (mode 0)
    k_gemmB<<<tiles, 128, GEMMB_SMEM>>>(x, encW, encB, nullptr, nullptr, nullptr,
                                        nullptr, gh, nullptr, N, 0, 0);

    for (int i = 0; i < 3; i++) {
        const float* zin = (i == 0) ? gh : gz;
        k_aggr<<<rowsW, 256>>>(zin, t, i, gs, N);
        k_mlp1<<<tiles, 256, MLP1_SMEM>>>(gs, W1 + i * 8192, b1 + i * 128,
                                          g1 + i * 128, bb1 + i * 128, ghid, N);
        if (i < 2) {
            // mlp2 + residual(if i>0) -> gh, plus z = relu(LN(h, ng[i+1])) -> gz
            k_gemmB<<<tiles, 128, GEMMB_SMEM>>>(ghid, W2 + i * 8192, b2 + i * 64,
                                                ng + (i + 1) * 64, nb + (i + 1) * 64,
                                                nullptr, nullptr, gh, gz, N, i ? 1 : 0, 1);
        } else {
            // last layer: residual + final LN(ng[0]) + ReLU -> out, head -> out tail
            k_gemmB<<<tiles, 128, GEMMB_SMEM>>>(ghid, W2 + i * 8192, b2 + i * 64,
                                                ng, nb, lw, lb, gh, out, N, 1, 2);
        }
    }
}

// round 5
// speedup vs baseline: 1.2021x; 1.2021x over previous
#include <cuda_runtime.h>

// ---------------------------------------------------------------------------
// DeeperGCN round 5:
//  - f32x2 packed-FMA SGEMMs with 8x8 micro-tiles (1.0 smem-B/MAC balance)
//  - gemmB: 64 thr / 64x64 tile / 3 CTA/SM;  mlp1: 128 thr / 64x128 / 3 CTA/SM
//  - aggregation exp on MUFU (ex2.approx), L2-bound gather
//  - preprocessing vectorized 4 edges/thread
// ---------------------------------------------------------------------------

#define NMAX 50048
#define EMAX 800000
typedef unsigned long long u64;

__device__ int   g_is64;
__device__ int   g_src[EMAX];
__device__ int   g_dst[EMAX];
__device__ int   g_ssrc[EMAX];
__device__ int   g_deg[NMAX];
__device__ int   g_off[NMAX];
__device__ int   g_cur[NMAX];
__device__ float g_h  [NMAX * 64];
__device__ float g_z  [NMAX * 64];
__device__ float g_s  [NMAX * 64];
__device__ float g_hid[NMAX * 128];

__device__ __forceinline__ void ffma2(u64 &d, u64 a, u64 b) {
    asm("fma.rn.f32x2 %0, %1, %2, %0;" : "+l"(d) : "l"(a), "l"(b));
}
__device__ __forceinline__ u64 pack2(float lo, float hi) {
    u64 r; asm("mov.b64 %0, {%1, %2};" : "=l"(r) : "f"(lo), "f"(hi)); return r;
}
__device__ __forceinline__ float2 unpack2(u64 v) {
    float2 r; asm("mov.b64 {%0, %1}, %2;" : "=f"(r.x), "=f"(r.y) : "l"(v)); return r;
}
__device__ __forceinline__ float ex2f(float x) {
    float r; asm("ex2.approx.f32 %0, %1;" : "=f"(r) : "f"(x)); return r;
}

// ---------------------------------------------------------------------------
// Edge preprocessing
// ---------------------------------------------------------------------------
__global__ void k_detect(const int* __restrict__ w, int E) {
    int lane = threadIdx.x;
    int bad = 0;
    int lim = min(128, E);
    for (int i = lane; i < lim; i += 32) bad |= w[2 * i + 1];
    unsigned b = __ballot_sync(0xffffffffu, bad != 0);
    if (lane == 0) g_is64 = (b == 0) ? 1 : 0;
}

__global__ void k_normcount(const void* __restrict__ raw, int E) {
    int base = (blockIdx.x * blockDim.x + threadIdx.x) * 4;
    if (base >= E) return;
    if (g_is64) {
        const long long* p = (const long long*)raw;
        #pragma unroll
        for (int j = 0; j < 4; j++) {
            int e = base + j;
            if (e < E) {
                int s = (int)p[e], d = (int)p[(size_t)E + e];
                g_src[e] = s; g_dst[e] = d;
                atomicAdd(&g_deg[d], 1);
            }
        }
    } else {
        const int* p = (const int*)raw;
        #pragma unroll
        for (int j = 0; j < 4; j++) {
            int e = base + j;
            if (e < E) {
                int s = p[e], d = p[(size_t)E + e];
                g_src[e] = s; g_dst[e] = d;
                atomicAdd(&g_deg[d], 1);
            }
        }
    }
}

__global__ void k_scan(int n) {
    __shared__ int sm[1024];
    int t = threadIdx.x;
    int IT = (n + 1023) >> 10;
    int base = t * IT;
    int s = 0;
    for (int i = 0; i < IT; i++) { int id = base + i; if (id < n) s += g_deg[id]; }
    sm[t] = s;
    __syncthreads();
    for (int off = 1; off < 1024; off <<= 1) {
        int v = (t >= off) ? sm[t - off] : 0;
        __syncthreads();
        sm[t] += v;
        __syncthreads();
    }
    int pre = (t == 0) ? 0 : sm[t - 1];
    for (int i = 0; i < IT; i++) {
        int id = base + i;
        if (id < n) { g_off[id] = pre; g_cur[id] = pre; pre += g_deg[id]; }
    }
}

__global__ void k_scatter(int E) {
    int base = (blockIdx.x * blockDim.x + threadIdx.x) * 4;
    if (base >= E) return;
    #pragma unroll
    for (int j = 0; j < 4; j++) {
        int e = base + j;
        if (e < E) {
            int d = g_dst[e];
            int pos = atomicAdd(&g_cur[d], 1);
            g_ssrc[pos] = g_src[e];
        }
    }
}

// ---------------------------------------------------------------------------
// Softmax aggregation, warp per destination node. Exp via MUFU (ex2.approx).
// eps folded into epilogue; max-subtraction omitted (identical ratio).
// ---------------------------------------------------------------------------
__global__ void k_aggr(const float* __restrict__ z, const float* __restrict__ tp,
                       int li, float* __restrict__ so, int N) {
    int w = (blockIdx.x * blockDim.x + threadIdx.x) >> 5;
    int lane = threadIdx.x & 31;
    if (w >= N) return;
    float tl = __ldg(tp + li) * 1.4426950408889634f;
    int beg = g_off[w], dg = g_deg[w];
    const float2* z2 = (const float2*)z;
    float se0 = 0.f, se1 = 0.f, sn0 = 0.f, sn1 = 0.f;
    #pragma unroll 4
    for (int j = 0; j < dg; j++) {
        int s = __ldg(&g_ssrc[beg + j]);
        float2 v = __ldg(&z2[(size_t)s * 32 + lane]);
        float m0 = fmaxf(v.x, 0.f);
        float m1 = fmaxf(v.y, 0.f);
        float e0 = ex2f(m0 * tl);
        float e1 = ex2f(m1 * tl);
        se0 += e0; se1 += e1;
        sn0 = fmaf(m0, e0, sn0);
        sn1 = fmaf(m1, e1, sn1);
    }
    float2 zd = __ldg(&z2[(size_t)w * 32 + lane]);
    float2 o;
    o.x = zd.x + fmaf(1e-7f, se0, sn0) / (se0 + 1e-16f);
    o.y = zd.y + fmaf(1e-7f, se1, sn1) / (se1 + 1e-16f);
    ((float2*)so)[(size_t)w * 32 + lane] = o;
}

// ---------------------------------------------------------------------------
// gemmB: [N,128] @ [128,64] + bias (+residual, +LN epilogue, +head)
// 64 threads (8 tr x 8 tc), tile 64 rows x 64 cols, 8 rows x 8 cols per thread
// cols per thread: [tc*4 .. tc*4+3] and [32+tc*4 .. 32+tc*4+3]
// modes: 0 plain->h_out; 1 ->h_out and z_out=relu(LN); 2 ->z_out + head tail
// ---------------------------------------------------------------------------
#define GEMMB_SMEM ((8192 + 8192 + 3 * 64 + 208) * 4)
__global__ __launch_bounds__(64) void k_gemmB(
    const float* __restrict__ A, const float* __restrict__ W,
    const float* __restrict__ bias, const float* __restrict__ lg,
    const float* __restrict__ lb, const float* __restrict__ lw,
    const float* __restrict__ lhb, float* __restrict__ h_out,
    float* __restrict__ z_out, int N, int addres, int mode) {
    extern __shared__ float sm[];
    float* As  = sm;             // 8192 (64 rows x 128 K)
    float* Ws  = sm + 8192;      // 8192 (128 K x 64 cols)
    float* bs  = sm + 16384;     // 64
    float* gs  = bs + 64;
    float* bb  = gs + 64;
    float* lws = bb + 64;        // 208 (192 used)
    int tid = threadIdx.x;
    {
        const float4* w4 = (const float4*)W;
        float4* s4 = (float4*)Ws;
        #pragma unroll
        for (int i = 0; i < 32; i++) s4[tid + i * 64] = w4[tid + i * 64];
        bs[tid] = bias[tid];
        if (mode) { gs[tid] = lg[tid]; bb[tid] = lb[tid]; }
        if (mode == 2 && tid < 48) ((float4*)lws)[tid] = ((const float4*)lw)[tid];
    }
    int r0 = blockIdx.x * 64;
    {
        const float4* a4 = (const float4*)A;
        float4* s4 = (float4*)As;
        #pragma unroll
        for (int i = 0; i < 32; i++) {
            int idx = tid + i * 64;                // 64 rows x 32 f4
            int row = min(r0 + (idx >> 5), N - 1);
            s4[idx] = __ldg(&a4[(size_t)row * 32 + (idx & 31)]);
        }
    }
    __syncthreads();
    int tr = tid >> 3, tc = tid & 7;
    u64 acc[8][4];
    #pragma unroll
    for (int r = 0; r < 8; r++)
        #pragma unroll
        for (int c = 0; c < 4; c++) acc[r][c] = 0ull;
    const float4* As4 = (const float4*)As;
    const ulonglong2* Ws2 = (const ulonglong2*)Ws;   // 16 ull2 per K-row
    #pragma unroll
    for (int k4 = 0; k4 < 32; k4++) {
        float4 a[8];
        #pragma unroll
        for (int r = 0; r < 8; r++) a[r] = As4[(tr * 8 + r) * 32 + k4];
        #pragma unroll
        for (int kk = 0; kk < 4; kk++) {
            int k = k4 * 4 + kk;
            ulonglong2 w0 = Ws2[k * 16 + tc];
            ulonglong2 w1 = Ws2[k * 16 + 8 + tc];
            #pragma unroll
            for (int r = 0; r < 8; r++) {
                float av = (kk == 0) ? a[r].x : (kk == 1) ? a[r].y :
                           (kk == 2) ? a[r].z : a[r].w;
                u64 av2 = pack2(av, av);
                ffma2(acc[r][0], av2, w0.x);
                ffma2(acc[r][1], av2, w0.y);
                ffma2(acc[r][2], av2, w1.x);
                ffma2(acc[r][3], av2, w1.y);
            }
        }
    }
    float4 bv0 = ((const float4*)bs)[tc], bv1 = ((const float4*)bs)[8 + tc];
    #pragma unroll
    for (int r = 0; r < 8; r++) {
        int rr = r0 + tr * 8 + r;
        bool ok = rr < N;
        float y[8];
        { float2 f = unpack2(acc[r][0]); y[0] = f.x + bv0.x; y[1] = f.y + bv0.y; }
        { float2 f = unpack2(acc[r][1]); y[2] = f.x + bv0.z; y[3] = f.y + bv0.w; }
        { float2 f = unpack2(acc[r][2]); y[4] = f.x + bv1.x; y[5] = f.y + bv1.y; }
        { float2 f = unpack2(acc[r][3]); y[6] = f.x + bv1.z; y[7] = f.y + bv1.w; }
        if (addres && ok) {
            float4 h0 = ((const float4*)h_out)[(size_t)rr * 16 + tc];
            float4 h1 = ((const float4*)h_out)[(size_t)rr * 16 + 8 + tc];
            y[0] += h0.x; y[1] += h0.y; y[2] += h0.z; y[3] += h0.w;
            y[4] += h1.x; y[5] += h1.y; y[6] += h1.z; y[7] += h1.w;
        }
        if (mode != 2 && ok) {
            float4 s0, s1;
            s0.x = y[0]; s0.y = y[1]; s0.z = y[2]; s0.w = y[3];
            s1.x = y[4]; s1.y = y[5]; s1.z = y[6]; s1.w = y[7];
            ((float4*)h_out)[(size_t)rr * 16 + tc]     = s0;
            ((float4*)h_out)[(size_t)rr * 16 + 8 + tc] = s1;
        }
        if (mode) {
            float s = 0.f, q = 0.f;
            #pragma unroll
            for (int c = 0; c < 8; c++) { s += y[c]; q = fmaf(y[c], y[c], q); }
            #pragma unroll
            for (int o = 1; o < 8; o <<= 1) {
                s += __shfl_xor_sync(0xffffffffu, s, o);
                q += __shfl_xor_sync(0xffffffffu, q, o);
            }
            float mu = s * (1.f / 64.f);
            float var = q * (1.f / 64.f) - mu * mu;
            float rs = rsqrtf(var + 1e-5f);
            float4 gv0 = ((const float4*)gs)[tc], gv1 = ((const float4*)gs)[8 + tc];
            float4 cv0 = ((const float4*)bb)[tc], cv1 = ((const float4*)bb)[8 + tc];
            float o8[8];
            o8[0] = fmaxf((y[0] - mu) * rs * gv0.x + cv0.x, 0.f);
            o8[1] = fmaxf((y[1] - mu) * rs * gv0.y + cv0.y, 0.f);
            o8[2] = fmaxf((y[2] - mu) * rs * gv0.z + cv0.z, 0.f);
            o8[3] = fmaxf((y[3] - mu) * rs * gv0.w + cv0.w, 0.f);
            o8[4] = fmaxf((y[4] - mu) * rs * gv1.x + cv1.x, 0.f);
            o8[5] = fmaxf((y[5] - mu) * rs * gv1.y + cv1.y, 0.f);
            o8[6] = fmaxf((y[6] - mu) * rs * gv1.z + cv1.z, 0.f);
            o8[7] = fmaxf((y[7] - mu) * rs * gv1.w + cv1.w, 0.f);
            if (ok) {
                float4 z0, z1;
                z0.x = o8[0]; z0.y = o8[1]; z0.z = o8[2]; z0.w = o8[3];
                z1.x = o8[4]; z1.y = o8[5]; z1.z = o8[6]; z1.w = o8[7];
                ((float4*)z_out)[(size_t)rr * 16 + tc]     = z0;
                ((float4*)z_out)[(size_t)rr * 16 + 8 + tc] = z1;
            }
            if (mode == 2) {
                float p0 = 0.f, p1 = 0.f, p2 = 0.f;
                #pragma unroll
                for (int j = 0; j < 4; j++) {
                    int c0 = tc * 4 + j, c1 = 32 + tc * 4 + j;
                    p0 = fmaf(o8[j], lws[c0 * 3 + 0], p0);
                    p1 = fmaf(o8[j], lws[c0 * 3 + 1], p1);
                    p2 = fmaf(o8[j], lws[c0 * 3 + 2], p2);
                    p0 = fmaf(o8[4 + j], lws[c1 * 3 + 0], p0);
                    p1 = fmaf(o8[4 + j], lws[c1 * 3 + 1], p1);
                    p2 = fmaf(o8[4 + j], lws[c1 * 3 + 2], p2);
                }
                #pragma unroll
                for (int o = 1; o < 8; o <<= 1) {
                    p0 += __shfl_xor_sync(0xffffffffu, p0, o);
                    p1 += __shfl_xor_sync(0xffffffffu, p1, o);
                    p2 += __shfl_xor_sync(0xffffffffu, p2, o);
                }
                if (tc == 0 && ok) {
                    size_t base = (size_t)N * 64 + (size_t)rr * 3;
                    z_out[base + 0] = p0 + __ldg(lhb + 0);
                    z_out[base + 1] = p1 + __ldg(lhb + 1);
                    z_out[base + 2] = p2 + __ldg(lhb + 2);
                }
            }
        }
    }
}

// ---------------------------------------------------------------------------
// mlp1: [N,64] @ [64,128] + bias -> LN(128) -> ReLU
// 128 threads (8 tr x 16 tc), tile 64 rows x 128 cols, 8r x 8c per thread
// cols per thread: [tc*4..+3] and [64+tc*4..+3]
// ---------------------------------------------------------------------------
#define MLP1_SMEM ((4096 + 8192 + 3 * 128) * 4)
__global__ __launch_bounds__(128) void k_mlp1(
    const float* __restrict__ A, const float* __restrict__ W,
    const float* __restrict__ bias, const float* __restrict__ lg,
    const float* __restrict__ lb, float* __restrict__ out, int N) {
    extern __shared__ float sm[];
    float* As  = sm;            // 4096 (64 rows x 64 K)
    float* Ws  = sm + 4096;     // 8192 (64 K x 128 cols)
    float* bs  = sm + 12288;    // 128
    float* gs  = bs + 128;
    float* bb  = gs + 128;
    int tid = threadIdx.x;
    {
        const float4* w4 = (const float4*)W;
        float4* s4 = (float4*)Ws;
        #pragma unroll
        for (int i = 0; i < 16; i++) s4[tid + i * 128] = w4[tid + i * 128];
        if (tid < 128) { bs[tid] = bias[tid]; gs[tid] = lg[tid]; bb[tid] = lb[tid]; }
    }
    int r0 = blockIdx.x * 64;
    {
        const float4* a4 = (const float4*)A;
        float4* s4 = (float4*)As;
        #pragma unroll
        for (int i = 0; i < 8; i++) {
            int idx = tid + i * 128;               // 64 rows x 16 f4
            int row = min(r0 + (idx >> 4), N - 1);
            s4[idx] = __ldg(&a4[(size_t)row * 16 + (idx & 15)]);
        }
    }
    __syncthreads();
    int tr = tid >> 4, tc = tid & 15;
    u64 acc[8][4];
    #pragma unroll
    for (int r = 0; r < 8; r++)
        #pragma unroll
        for (int c = 0; c < 4; c++) acc[r][c] = 0ull;
    const float4* As4 = (const float4*)As;
    const ulonglong2* Ws2 = (const ulonglong2*)Ws;  // 32 ull2 per K-row
    #pragma unroll
    for (int k4 = 0; k4 < 16; k4++) {
        float4 a[8];
        #pragma unroll
        for (int r = 0; r < 8; r++) a[r] = As4[(tr * 8 + r) * 16 + k4];
        #pragma unroll
        for (int kk = 0; kk < 4; kk++) {
            int k = k4 * 4 + kk;
            ulonglong2 w0 = Ws2[k * 32 + tc];
            ulonglong2 w1 = Ws2[k * 32 + 16 + tc];
            #pragma unroll
            for (int r = 0; r < 8; r++) {
                float av = (kk == 0) ? a[r].x : (kk == 1) ? a[r].y :
                           (kk == 2) ? a[r].z : a[r].w;
                u64 av2 = pack2(av, av);
                ffma2(acc[r][0], av2, w0.x);
                ffma2(acc[r][1], av2, w0.y);
                ffma2(acc[r][2], av2, w1.x);
                ffma2(acc[r][3], av2, w1.y);
            }
        }
    }
    float4 bv0 = ((const float4*)bs)[tc], bv1 = ((const float4*)bs)[16 + tc];
    float4 gv0 = ((const float4*)gs)[tc], gv1 = ((const float4*)gs)[16 + tc];
    float4 cv0 = ((const float4*)bb)[tc], cv1 = ((const float4*)bb)[16 + tc];
    #pragma unroll
    for (int r = 0; r < 8; r++) {
        int rr = r0 + tr * 8 + r;
        float y[8];
        { float2 f = unpack2(acc[r][0]); y[0] = f.x + bv0.x; y[1] = f.y + bv0.y; }
        { float2 f = unpack2(acc[r][1]); y[2] = f.x + bv0.z; y[3] = f.y + bv0.w; }
        { float2 f = unpack2(acc[r][2]); y[4] = f.x + bv1.x; y[5] = f.y + bv1.y; }
        { float2 f = unpack2(acc[r][3]); y[6] = f.x + bv1.z; y[7] = f.y + bv1.w; }
        float s = 0.f, q = 0.f;
        #pragma unroll
        for (int c = 0; c < 8; c++) { s += y[c]; q = fmaf(y[c], y[c], q); }
        #pragma unroll
        for (int o = 1; o < 16; o <<= 1) {
            s += __shfl_xor_sync(0xffffffffu, s, o);
            q += __shfl_xor_sync(0xffffffffu, q, o);
        }
        float mu = s * (1.f / 128.f);
        float var = q * (1.f / 128.f) - mu * mu;
        float rs = rsqrtf(var + 1e-5f);
        float4 o0, o1;
        o0.x = fmaxf((y[0] - mu) * rs * gv0.x + cv0.x, 0.f);
        o0.y = fmaxf((y[1] - mu) * rs * gv0.y + cv0.y, 0.f);
        o0.z = fmaxf((y[2] - mu) * rs * gv0.z + cv0.z, 0.f);
        o0.w = fmaxf((y[3] - mu) * rs * gv0.w + cv0.w, 0.f);
        o1.x = fmaxf((y[4] - mu) * rs * gv1.x + cv1.x, 0.f);
        o1.y = fmaxf((y[5] - mu) * rs * gv1.y + cv1.y, 0.f);
        o1.z = fmaxf((y[6] - mu) * rs * gv1.z + cv1.z, 0.f);
        o1.w = fmaxf((y[7] - mu) * rs * gv1.w + cv1.w, 0.f);
        if (rr < N) {
            ((float4*)out)[(size_t)rr * 32 + tc]      = o0;
            ((float4*)out)[(size_t)rr * 32 + 16 + tc] = o1;
        }
    }
}

// ---------------------------------------------------------------------------
// Host launch
// ---------------------------------------------------------------------------
extern "C" void kernel_launch(void* const* d_in, const int* in_sizes, int n_in,
                              void* d_out, int out_size) {
    const float* x    = (const float*)d_in[0];
    const void*  ei   = d_in[1];
    const float* encW = (const float*)d_in[2];
    const float* encB = (const float*)d_in[3];
    const float* t    = (const float*)d_in[4];
    const float* W1   = (const float*)d_in[5];
    const float* b1   = (const float*)d_in[6];
    const float* g1   = (const float*)d_in[7];
    const float* bb1  = (const float*)d_in[8];
    const float* W2   = (const float*)d_in[9];
    const float* b2   = (const float*)d_in[10];
    const float* ng   = (const float*)d_in[11];
    const float* nb   = (const float*)d_in[12];
    const float* lw   = (const float*)d_in[13];
    const float* lb   = (const float*)d_in[14];
    int N = in_sizes[0] / 128;
    int E = in_sizes[1] / 2;
    if (N > NMAX) N = NMAX;
    if (E > EMAX) E = EMAX;
    float* out = (float*)d_out;

    cudaFuncSetAttribute(k_mlp1,  cudaFuncAttributeMaxDynamicSharedMemorySize, MLP1_SMEM);
    cudaFuncSetAttribute(k_gemmB, cudaFuncAttributeMaxDynamicSharedMemorySize, GEMMB_SMEM);

    float *gh, *gz, *gs, *ghid;
    int *gdeg;
    cudaGetSymbolAddress((void**)&gh,   g_h);
    cudaGetSymbolAddress((void**)&gz,   g_z);
    cudaGetSymbolAddress((void**)&gs,   g_s);
    cudaGetSymbolAddress((void**)&ghid, g_hid);
    cudaGetSymbolAddress((void**)&gdeg, g_deg);

    int eb4 = (E + 1023) / 1024;   // 4 edges/thread, 256 threads
    int rowsW = (N + 7) / 8;       // warp-per-node aggr, 256 threads
    int tiles = (N + 63) / 64;

    // edge preprocessing (CSR by dst)
    cudaMemsetAsync(gdeg, 0, (size_t)N * sizeof(int));
    k_detect<<<1, 32>>>((const int*)ei, E);
    k_normcount<<<eb4, 256>>>(ei, E);
    k_scan<<<1, 1024>>>(N);
    k_scatter<<<eb4, 256>>>(E);

    // encoder: x @ encW + encB -> gh  (mode 0)
    k_gemmB<<<tiles, 64, GEMMB_SMEM>>>(x, encW, encB, nullptr, nullptr, nullptr,
                                       nullptr, gh, nullptr, N, 0, 0);

    for (int i = 0; i < 3; i++) {
        const float* zin = (i == 0) ? gh : gz;
        k_aggr<<<rowsW, 256>>>(zin, t, i, gs, N);
        k_mlp1<<<tiles, 128, MLP1_SMEM>>>(gs, W1 + i * 8192, b1 + i * 128,
                                          g1 + i * 128, bb1 + i * 128, ghid, N);
        if (i < 2) {
            // mlp2 + residual(if i>0) -> gh, plus z = relu(LN(h, ng[i+1])) -> gz
            k_gemmB<<<tiles, 64, GEMMB_SMEM>>>(ghid, W2 + i * 8192, b2 + i * 64,
                                               ng + (i + 1) * 64, nb + (i + 1) * 64,
                                               nullptr, nullptr, gh, gz, N, i ? 1 : 0, 1);
        } else {
            // last layer: residual + final LN(ng[0]) + ReLU -> out, head -> out tail
            k_gemmB<<<tiles, 64, GEMMB_SMEM>>>(ghid, W2 + i * 8192, b2 + i * 64,
                                               ng, nb, lw, lb, gh, out, N, 1, 2);
        }
    }
}

// round 6
// speedup vs baseline: 1.4981x; 1.2462x over previous
#include <cuda_runtime.h>
#include <cuda_fp16.h>

// ---------------------------------------------------------------------------
// DeeperGCN round 6:
//  - fp16 mirror of z for the edge gather (halves dominant L2 traffic)
//  - gemmB: 128 thr / 128x64 tile (8 warps/SM, 1.32 waves), f32x2 packed FMA
//  - two-level shfl scan; packed int2 edges; partial offsets folded into
//    scatter/aggr
// ---------------------------------------------------------------------------

#define NMAX 50048
#define EMAX 800000
typedef unsigned long long u64;

__device__ int      g_is64;
__device__ int2     g_edge[EMAX];
__device__ int      g_ssrc[EMAX];
__device__ int      g_deg[NMAX];
__device__ int      g_off[NMAX];
__device__ int      g_cur[NMAX];
__device__ int      g_part[64];
__device__ unsigned g_zh [NMAX * 32];     // half2 per entry (64 feats / row)
__device__ float    g_h  [NMAX * 64];
__device__ float    g_s  [NMAX * 64];
__device__ float    g_hid[NMAX * 128];

__device__ __forceinline__ void ffma2(u64 &d, u64 a, u64 b) {
    asm("fma.rn.f32x2 %0, %1, %2, %0;" : "+l"(d) : "l"(a), "l"(b));
}
__device__ __forceinline__ u64 pack2(float lo, float hi) {
    u64 r; asm("mov.b64 %0, {%1, %2};" : "=l"(r) : "f"(lo), "f"(hi)); return r;
}
__device__ __forceinline__ float2 unpack2(u64 v) {
    float2 r; asm("mov.b64 {%0, %1}, %2;" : "=f"(r.x), "=f"(r.y) : "l"(v)); return r;
}
__device__ __forceinline__ float ex2f(float x) {
    float r; asm("ex2.approx.f32 %0, %1;" : "=f"(r) : "f"(x)); return r;
}
__device__ __forceinline__ unsigned h2pack(float a, float b) {
    __half2 h = __floats2half2_rn(a, b);
    return *(unsigned*)&h;
}
__device__ __forceinline__ float2 h2unpack(unsigned u) {
    __half2 h = *(__half2*)&u;
    return __half22float2(h);
}

// ---------------------------------------------------------------------------
// Edge preprocessing
// ---------------------------------------------------------------------------
__global__ void k_detect(const int* __restrict__ w, int E) {
    int lane = threadIdx.x;
    int bad = 0;
    int lim = min(128, E);
    for (int i = lane; i < lim; i += 32) bad |= w[2 * i + 1];
    unsigned b = __ballot_sync(0xffffffffu, bad != 0);
    if (lane == 0) g_is64 = (b == 0) ? 1 : 0;
}

__global__ void k_normcount(const void* __restrict__ raw, int E) {
    int base = (blockIdx.x * blockDim.x + threadIdx.x) * 4;
    if (base >= E) return;
    if (g_is64) {
        const long long* p = (const long long*)raw;
        #pragma unroll
        for (int j = 0; j < 4; j++) {
            int e = base + j;
            if (e < E) {
                int s = (int)p[e], d = (int)p[(size_t)E + e];
                g_edge[e] = make_int2(s, d);
                atomicAdd(&g_deg[d], 1);
            }
        }
    } else {
        const int* p = (const int*)raw;
        #pragma unroll
        for (int j = 0; j < 4; j++) {
            int e = base + j;
            if (e < E) {
                int s = p[e], d = p[(size_t)E + e];
                g_edge[e] = make_int2(s, d);
                atomicAdd(&g_deg[d], 1);
            }
        }
    }
}

// two-level scan: per-1024-block exclusive scan + block partial
__global__ void k_scan1(int n) {
    __shared__ int wsum[32];
    int tid = threadIdx.x;
    int i = blockIdx.x * 1024 + tid;
    int v = (i < n) ? g_deg[i] : 0;
    int lane = tid & 31, wid = tid >> 5;
    int s = v;
    #pragma unroll
    for (int o = 1; o < 32; o <<= 1) {
        int t = __shfl_up_sync(0xffffffffu, s, o);
        if (lane >= o) s += t;
    }
    if (lane == 31) wsum[wid] = s;
    __syncthreads();
    if (wid == 0) {
        int w = wsum[lane];
        #pragma unroll
        for (int o = 1; o < 32; o <<= 1) {
            int t = __shfl_up_sync(0xffffffffu, w, o);
            if (lane >= o) w += t;
        }
        wsum[lane] = w;
    }
    __syncthreads();
    int base = wid ? wsum[wid - 1] : 0;
    int excl = base + s - v;
    if (i < n) { g_off[i] = excl; g_cur[i] = excl; }
    if (tid == 1023) g_part[blockIdx.x] = base + s;
}

__global__ void k_scan2(int P) {
    __shared__ int s[64];
    int tid = threadIdx.x;
    s[tid] = (tid < P) ? g_part[tid] : 0;
    __syncthreads();
    if (tid == 0) {
        int acc = 0;
        for (int i = 0; i < P; i++) { int v = s[i]; s[i] = acc; acc += v; }
    }
    __syncthreads();
    if (tid < P) g_part[tid] = s[tid];
}

__global__ void k_scatter(int E) {
    int base = (blockIdx.x * blockDim.x + threadIdx.x) * 4;
    if (base >= E) return;
    #pragma unroll
    for (int j = 0; j < 4; j++) {
        int e = base + j;
        if (e < E) {
            int2 ed = g_edge[e];
            int pos = atomicAdd(&g_cur[ed.y], 1) + g_part[ed.y >> 10];
            g_ssrc[pos] = ed.x;
        }
    }
}

// ---------------------------------------------------------------------------
// Softmax aggregation, warp per destination node, fp16 gather.
// eps folded into epilogue; max-subtraction omitted (identical ratio).
// ---------------------------------------------------------------------------
__global__ void k_aggr(const float* __restrict__ tp, int li,
                       float* __restrict__ so, int N) {
    int w = (blockIdx.x * blockDim.x + threadIdx.x) >> 5;
    int lane = threadIdx.x & 31;
    if (w >= N) return;
    float tl = __ldg(tp + li) * 1.4426950408889634f;
    int beg = g_off[w] + g_part[w >> 10];
    int dg = g_deg[w];
    float se0 = 0.f, se1 = 0.f, sn0 = 0.f, sn1 = 0.f;
    #pragma unroll 4
    for (int j = 0; j < dg; j++) {
        int s = __ldg(&g_ssrc[beg + j]);
        float2 v = h2unpack(__ldg(&g_zh[(size_t)s * 32 + lane]));
        float m0 = fmaxf(v.x, 0.f);
        float m1 = fmaxf(v.y, 0.f);
        float e0 = ex2f(m0 * tl);
        float e1 = ex2f(m1 * tl);
        se0 += e0; se1 += e1;
        sn0 = fmaf(m0, e0, sn0);
        sn1 = fmaf(m1, e1, sn1);
    }
    float2 zd = h2unpack(g_zh[(size_t)w * 32 + lane]);
    float2 o;
    o.x = zd.x + fmaf(1e-7f, se0, sn0) / (se0 + 1e-16f);
    o.y = zd.y + fmaf(1e-7f, se1, sn1) / (se1 + 1e-16f);
    ((float2*)so)[(size_t)w * 32 + lane] = o;
}

// ---------------------------------------------------------------------------
// gemmB: [N,128] @ [128,64] + bias (+residual, +LN epilogue, +head)
// 128 threads (16 tr x 8 tc), tile 128 rows x 64 cols, 8x8 per thread
// modes: 0 encoder -> zh only; 1 -> h_out fp32 + zh = relu(LN);
//        2 -> z_out = relu(LN) fp32 + head tail (final output)
// ---------------------------------------------------------------------------
#define GEMMB_SMEM ((16384 + 8192 + 3 * 64 + 208) * 4)
__global__ __launch_bounds__(128) void k_gemmB(
    const float* __restrict__ A, const float* __restrict__ W,
    const float* __restrict__ bias, const float* __restrict__ lg,
    const float* __restrict__ lb, const float* __restrict__ lw,
    const float* __restrict__ lhb, float* __restrict__ h_out,
    float* __restrict__ z_out, int N, int addres, int mode) {
    extern __shared__ float sm[];
    float* As  = sm;             // 16384 (128 rows x 128 K)
    float* Ws  = sm + 16384;     // 8192  (128 K x 64 cols)
    float* bs  = sm + 24576;     // 64
    float* gs  = bs + 64;
    float* bb  = gs + 64;
    float* lws = bb + 64;        // 208 (192 used)
    int tid = threadIdx.x;
    {
        const float4* w4 = (const float4*)W;
        float4* s4 = (float4*)Ws;
        #pragma unroll
        for (int i = 0; i < 16; i++) s4[tid + i * 128] = w4[tid + i * 128];
        if (tid < 64) {
            bs[tid] = bias[tid];
            if (mode) { gs[tid] = lg[tid]; bb[tid] = lb[tid]; }
        }
        if (mode == 2 && tid < 48) ((float4*)lws)[tid] = ((const float4*)lw)[tid];
    }
    int r0 = blockIdx.x * 128;
    {
        const float4* a4 = (const float4*)A;
        float4* s4 = (float4*)As;
        #pragma unroll
        for (int i = 0; i < 32; i++) {
            int idx = tid + i * 128;               // 128 rows x 32 f4
            int row = min(r0 + (idx >> 5), N - 1);
            s4[idx] = __ldg(&a4[(size_t)row * 32 + (idx & 31)]);
        }
    }
    __syncthreads();
    int tr = tid >> 3, tc = tid & 7;
    u64 acc[8][4];
    #pragma unroll
    for (int r = 0; r < 8; r++)
        #pragma unroll
        for (int c = 0; c < 4; c++) acc[r][c] = 0ull;
    const float4* As4 = (const float4*)As;
    const ulonglong2* Ws2 = (const ulonglong2*)Ws;   // 16 ull2 per K-row
    #pragma unroll
    for (int k4 = 0; k4 < 32; k4++) {
        float4 a[8];
        #pragma unroll
        for (int r = 0; r < 8; r++) a[r] = As4[(tr * 8 + r) * 32 + k4];
        #pragma unroll
        for (int kk = 0; kk < 4; kk++) {
            int k = k4 * 4 + kk;
            ulonglong2 w0 = Ws2[k * 16 + tc];
            ulonglong2 w1 = Ws2[k * 16 + 8 + tc];
            #pragma unroll
            for (int r = 0; r < 8; r++) {
                float av = (kk == 0) ? a[r].x : (kk == 1) ? a[r].y :
                           (kk == 2) ? a[r].z : a[r].w;
                u64 av2 = pack2(av, av);
                ffma2(acc[r][0], av2, w0.x);
                ffma2(acc[r][1], av2, w0.y);
                ffma2(acc[r][2], av2, w1.x);
                ffma2(acc[r][3], av2, w1.y);
            }
        }
    }
    float4 bv0 = ((const float4*)bs)[tc], bv1 = ((const float4*)bs)[8 + tc];
    #pragma unroll
    for (int r = 0; r < 8; r++) {
        int rr = r0 + tr * 8 + r;
        bool ok = rr < N;
        float y[8];
        { float2 f = unpack2(acc[r][0]); y[0] = f.x + bv0.x; y[1] = f.y + bv0.y; }
        { float2 f = unpack2(acc[r][1]); y[2] = f.x + bv0.z; y[3] = f.y + bv0.w; }
        { float2 f = unpack2(acc[r][2]); y[4] = f.x + bv1.x; y[5] = f.y + bv1.y; }
        { float2 f = unpack2(acc[r][3]); y[6] = f.x + bv1.z; y[7] = f.y + bv1.w; }
        if (addres && ok) {
            float4 h0 = ((const float4*)h_out)[(size_t)rr * 16 + tc];
            float4 h1 = ((const float4*)h_out)[(size_t)rr * 16 + 8 + tc];
            y[0] += h0.x; y[1] += h0.y; y[2] += h0.z; y[3] += h0.w;
            y[4] += h1.x; y[5] += h1.y; y[6] += h1.z; y[7] += h1.w;
        }
        if (mode == 0) {
            if (ok) {
                uint2* zh2 = (uint2*)g_zh;
                uint2 a0, a1;
                a0.x = h2pack(y[0], y[1]); a0.y = h2pack(y[2], y[3]);
                a1.x = h2pack(y[4], y[5]); a1.y = h2pack(y[6], y[7]);
                zh2[(size_t)rr * 16 + tc]     = a0;
                zh2[(size_t)rr * 16 + 8 + tc] = a1;
            }
            continue;
        }
        if (mode == 1 && ok) {
            float4 s0, s1;
            s0.x = y[0]; s0.y = y[1]; s0.z = y[2]; s0.w = y[3];
            s1.x = y[4]; s1.y = y[5]; s1.z = y[6]; s1.w = y[7];
            ((float4*)h_out)[(size_t)rr * 16 + tc]     = s0;
            ((float4*)h_out)[(size_t)rr * 16 + 8 + tc] = s1;
        }
        // LN(64) + ReLU epilogue (modes 1,2)
        float s = 0.f, q = 0.f;
        #pragma unroll
        for (int c = 0; c < 8; c++) { s += y[c]; q = fmaf(y[c], y[c], q); }
        #pragma unroll
        for (int o = 1; o < 8; o <<= 1) {
            s += __shfl_xor_sync(0xffffffffu, s, o);
            q += __shfl_xor_sync(0xffffffffu, q, o);
        }
        float mu = s * (1.f / 64.f);
        float var = q * (1.f / 64.f) - mu * mu;
        float rs = rsqrtf(var + 1e-5f);
        float4 gv0 = ((const float4*)gs)[tc], gv1 = ((const float4*)gs)[8 + tc];
        float4 cv0 = ((const float4*)bb)[tc], cv1 = ((const float4*)bb)[8 + tc];
        float o8[8];
        o8[0] = fmaxf((y[0] - mu) * rs * gv0.x + cv0.x, 0.f);
        o8[1] = fmaxf((y[1] - mu) * rs * gv0.y + cv0.y, 0.f);
        o8[2] = fmaxf((y[2] - mu) * rs * gv0.z + cv0.z, 0.f);
        o8[3] = fmaxf((y[3] - mu) * rs * gv0.w + cv0.w, 0.f);
        o8[4] = fmaxf((y[4] - mu) * rs * gv1.x + cv1.x, 0.f);
        o8[5] = fmaxf((y[5] - mu) * rs * gv1.y + cv1.y, 0.f);
        o8[6] = fmaxf((y[6] - mu) * rs * gv1.z + cv1.z, 0.f);
        o8[7] = fmaxf((y[7] - mu) * rs * gv1.w + cv1.w, 0.f);
        if (mode == 1) {
            if (ok) {
                uint2* zh2 = (uint2*)g_zh;
                uint2 a0, a1;
                a0.x = h2pack(o8[0], o8[1]); a0.y = h2pack(o8[2], o8[3]);
                a1.x = h2pack(o8[4], o8[5]); a1.y = h2pack(o8[6], o8[7]);
                zh2[(size_t)rr * 16 + tc]     = a0;
                zh2[(size_t)rr * 16 + 8 + tc] = a1;
            }
        } else {  // mode 2: final output + head
            if (ok) {
                float4 z0, z1;
                z0.x = o8[0]; z0.y = o8[1]; z0.z = o8[2]; z0.w = o8[3];
                z1.x = o8[4]; z1.y = o8[5]; z1.z = o8[6]; z1.w = o8[7];
                ((float4*)z_out)[(size_t)rr * 16 + tc]     = z0;
                ((float4*)z_out)[(size_t)rr * 16 + 8 + tc] = z1;
            }
            float p0 = 0.f, p1 = 0.f, p2 = 0.f;
            #pragma unroll
            for (int j = 0; j < 4; j++) {
                int c0 = tc * 4 + j, c1 = 32 + tc * 4 + j;
                p0 = fmaf(o8[j], lws[c0 * 3 + 0], p0);
                p1 = fmaf(o8[j], lws[c0 * 3 + 1], p1);
                p2 = fmaf(o8[j], lws[c0 * 3 + 2], p2);
                p0 = fmaf(o8[4 + j], lws[c1 * 3 + 0], p0);
                p1 = fmaf(o8[4 + j], lws[c1 * 3 + 1], p1);
                p2 = fmaf(o8[4 + j], lws[c1 * 3 + 2], p2);
            }
            #pragma unroll
            for (int o = 1; o < 8; o <<= 1) {
                p0 += __shfl_xor_sync(0xffffffffu, p0, o);
                p1 += __shfl_xor_sync(0xffffffffu, p1, o);
                p2 += __shfl_xor_sync(0xffffffffu, p2, o);
            }
            if (tc == 0 && ok) {
                size_t base = (size_t)N * 64 + (size_t)rr * 3;
                z_out[base + 0] = p0 + __ldg(lhb + 0);
                z_out[base + 1] = p1 + __ldg(lhb + 1);
                z_out[base + 2] = p2 + __ldg(lhb + 2);
            }
        }
    }
}

// ---------------------------------------------------------------------------
// mlp1: [N,64] @ [64,128] + bias -> LN(128) -> ReLU
// 128 threads (8 tr x 16 tc), tile 64 rows x 128 cols, 8x8 per thread
// ---------------------------------------------------------------------------
#define MLP1_SMEM ((4096 + 8192 + 3 * 128) * 4)
__global__ __launch_bounds__(128) void k_mlp1(
    const float* __restrict__ A, const float* __restrict__ W,
    const float* __restrict__ bias, const float* __restrict__ lg,
    const float* __restrict__ lb, float* __restrict__ out, int N) {
    extern __shared__ float sm[];
    float* As  = sm;            // 4096 (64 rows x 64 K)
    float* Ws  = sm + 4096;     // 8192 (64 K x 128 cols)
    float* bs  = sm + 12288;    // 128
    float* gs  = bs + 128;
    float* bb  = gs + 128;
    int tid = threadIdx.x;
    {
        const float4* w4 = (const float4*)W;
        float4* s4 = (float4*)Ws;
        #pragma unroll
        for (int i = 0; i < 16; i++) s4[tid + i * 128] = w4[tid + i * 128];
        if (tid < 128) { bs[tid] = bias[tid]; gs[tid] = lg[tid]; bb[tid] = lb[tid]; }
    }
    int r0 = blockIdx.x * 64;
    {
        const float4* a4 = (const float4*)A;
        float4* s4 = (float4*)As;
        #pragma unroll
        for (int i = 0; i < 8; i++) {
            int idx = tid + i * 128;               // 64 rows x 16 f4
            int row = min(r0 + (idx >> 4), N - 1);
            s4[idx] = __ldg(&a4[(size_t)row * 16 + (idx & 15)]);
        }
    }
    __syncthreads();
    int tr = tid >> 4, tc = tid & 15;
    u64 acc[8][4];
    #pragma unroll
    for (int r = 0; r < 8; r++)
        #pragma unroll
        for (int c = 0; c < 4; c++) acc[r][c] = 0ull;
    const float4* As4 = (const float4*)As;
    const ulonglong2* Ws2 = (const ulonglong2*)Ws;  // 32 ull2 per K-row
    #pragma unroll
    for (int k4 = 0; k4 < 16; k4++) {
        float4 a[8];
        #pragma unroll
        for (int r = 0; r < 8; r++) a[r] = As4[(tr * 8 + r) * 16 + k4];
        #pragma unroll
        for (int kk = 0; kk < 4; kk++) {
            int k = k4 * 4 + kk;
            ulonglong2 w0 = Ws2[k * 32 + tc];
            ulonglong2 w1 = Ws2[k * 32 + 16 + tc];
            #pragma unroll
            for (int r = 0; r < 8; r++) {
                float av = (kk == 0) ? a[r].x : (kk == 1) ? a[r].y :
                           (kk == 2) ? a[r].z : a[r].w;
                u64 av2 = pack2(av, av);
                ffma2(acc[r][0], av2, w0.x);
                ffma2(acc[r][1], av2, w0.y);
                ffma2(acc[r][2], av2, w1.x);
                ffma2(acc[r][3], av2, w1.y);
            }
        }
    }
    float4 bv0 = ((const float4*)bs)[tc], bv1 = ((const float4*)bs)[16 + tc];
    float4 gv0 = ((const float4*)gs)[tc], gv1 = ((const float4*)gs)[16 + tc];
    float4 cv0 = ((const float4*)bb)[tc], cv1 = ((const float4*)bb)[16 + tc];
    #pragma unroll
    for (int r = 0; r < 8; r++) {
        int rr = r0 + tr * 8 + r;
        float y[8];
        { float2 f = unpack2(acc[r][0]); y[0] = f.x + bv0.x; y[1] = f.y + bv0.y; }
        { float2 f = unpack2(acc[r][1]); y[2] = f.x + bv0.z; y[3] = f.y + bv0.w; }
        { float2 f = unpack2(acc[r][2]); y[4] = f.x + bv1.x; y[5] = f.y + bv1.y; }
        { float2 f = unpack2(acc[r][3]); y[6] = f.x + bv1.z; y[7] = f.y + bv1.w; }
        float s = 0.f, q = 0.f;
        #pragma unroll
        for (int c = 0; c < 8; c++) { s += y[c]; q = fmaf(y[c], y[c], q); }
        #pragma unroll
        for (int o = 1; o < 16; o <<= 1) {
            s += __shfl_xor_sync(0xffffffffu, s, o);
            q += __shfl_xor_sync(0xffffffffu, q, o);
        }
        float mu = s * (1.f / 128.f);
        float var = q * (1.f / 128.f) - mu * mu;
        float rs = rsqrtf(var + 1e-5f);
        float4 o0, o1;
        o0.x = fmaxf((y[0] - mu) * rs * gv0.x + cv0.x, 0.f);
        o0.y = fmaxf((y[1] - mu) * rs * gv0.y + cv0.y, 0.f);
        o0.z = fmaxf((y[2] - mu) * rs * gv0.z + cv0.z, 0.f);
        o0.w = fmaxf((y[3] - mu) * rs * gv0.w + cv0.w, 0.f);
        o1.x = fmaxf((y[4] - mu) * rs * gv1.x + cv1.x, 0.f);
        o1.y = fmaxf((y[5] - mu) * rs * gv1.y + cv1.y, 0.f);
        o1.z = fmaxf((y[6] - mu) * rs * gv1.z + cv1.z, 0.f);
        o1.w = fmaxf((y[7] - mu) * rs * gv1.w + cv1.w, 0.f);
        if (rr < N) {
            ((float4*)out)[(size_t)rr * 32 + tc]      = o0;
            ((float4*)out)[(size_t)rr * 32 + 16 + tc] = o1;
        }
    }
}

// ---------------------------------------------------------------------------
// Host launch
// ---------------------------------------------------------------------------
extern "C" void kernel_launch(void* const* d_in, const int* in_sizes, int n_in,
                              void* d_out, int out_size) {
    const float* x    = (const float*)d_in[0];
    const void*  ei   = d_in[1];
    const float* encW = (const float*)d_in[2];
    const float* encB = (const float*)d_in[3];
    const float* t    = (const float*)d_in[4];
    const float* W1   = (const float*)d_in[5];
    const float* b1   = (const float*)d_in[6];
    const float* g1   = (const float*)d_in[7];
    const float* bb1  = (const float*)d_in[8];
    const float* W2   = (const float*)d_in[9];
    const float* b2   = (const float*)d_in[10];
    const float* ng   = (const float*)d_in[11];
    const float* nb   = (const float*)d_in[12];
    const float* lw   = (const float*)d_in[13];
    const float* lb   = (const float*)d_in[14];
    int N = in_sizes[0] / 128;
    int E = in_sizes[1] / 2;
    if (N > NMAX) N = NMAX;
    if (E > EMAX) E = EMAX;
    float* out = (float*)d_out;

    cudaFuncSetAttribute(k_mlp1,  cudaFuncAttributeMaxDynamicSharedMemorySize, MLP1_SMEM);
    cudaFuncSetAttribute(k_gemmB, cudaFuncAttributeMaxDynamicSharedMemorySize, GEMMB_SMEM);

    float *gh, *gsv, *ghid;
    int *gdeg;
    cudaGetSymbolAddress((void**)&gh,   g_h);
    cudaGetSymbolAddress((void**)&gsv,  g_s);
    cudaGetSymbolAddress((void**)&ghid, g_hid);
    cudaGetSymbolAddress((void**)&gdeg, g_deg);

    int eb4     = (E + 1023) / 1024;   // 4 edges/thread, 256 threads
    int rowsW   = (N + 7) / 8;         // warp-per-node aggr, 256 threads
    int tiles64 = (N + 63) / 64;
    int tilesB  = (N + 127) / 128;
    int sblocks = (N + 1023) / 1024;

    // edge preprocessing (CSR by dst)
    cudaMemsetAsync(gdeg, 0, (size_t)N * sizeof(int));
    k_detect<<<1, 32>>>((const int*)ei, E);
    k_normcount<<<eb4, 256>>>(ei, E);
    k_scan1<<<sblocks, 1024>>>(N);
    k_scan2<<<1, 64>>>(sblocks);
    k_scatter<<<eb4, 256>>>(E);

    // encoder: x @ encW + encB -> zh (mode 0)
    k_gemmB<<<tilesB, 128, GEMMB_SMEM>>>(x, encW, encB, nullptr, nullptr,
                                         nullptr, nullptr, gh, nullptr, N, 0, 0);

    for (int i = 0; i < 3; i++) {
        k_aggr<<<rowsW, 256>>>(t, i, gsv, N);
        k_mlp1<<<tiles64, 128, MLP1_SMEM>>>(gsv, W1 + i * 8192, b1 + i * 128,
                                            g1 + i * 128, bb1 + i * 128, ghid, N);
        if (i < 2) {
            // mlp2 (+res if i>0) -> gh fp32; zh = relu(LN(gh, ng[i+1]))
            k_gemmB<<<tilesB, 128, GEMMB_SMEM>>>(ghid, W2 + i * 8192, b2 + i * 64,
                                                 ng + (i + 1) * 64, nb + (i + 1) * 64,
                                                 nullptr, nullptr, gh, nullptr,
                                                 N, i ? 1 : 0, 1);
        } else {
            // last: res + final LN(ng[0]) + ReLU -> out, head -> out tail
            k_gemmB<<<tilesB, 128, GEMMB_SMEM>>>(ghid, W2 + i * 8192, b2 + i * 64,
                                                 ng, nb, lw, lb, gh, out, N, 1, 2);
        }
    }
}

// round 7
// speedup vs baseline: 1.9352x; 1.2917x over previous
#include <cuda_runtime.h>
#include <cuda_fp16.h>

// ---------------------------------------------------------------------------
// DeeperGCN round 7:
//  - all GEMMs on tensor pipe: mma.sync.m16n8k8.tf32 (register MMA),
//    conflict-free padded-A smem + fragment-packed B smem, tf32 cvt at staging
//  - fused epilogues kept: bias/residual/LN(quad-shfl)/fp16 zh mirror/head
//  - fp16 edge gather + MUFU exp aggregation (r6, unchanged)
// ---------------------------------------------------------------------------

#define NMAX 50048
#define EMAX 800000
typedef unsigned long long u64;
typedef unsigned int u32;

__device__ int      g_is64;
__device__ int2     g_edge[EMAX];
__device__ int      g_ssrc[EMAX];
__device__ int      g_deg[NMAX];
__device__ int      g_off[NMAX];
__device__ int      g_cur[NMAX];
__device__ int      g_part[64];
__device__ unsigned g_zh [NMAX * 32];     // half2 per entry (64 feats / row)
__device__ float    g_h  [NMAX * 64];
__device__ float    g_s  [NMAX * 64];
__device__ float    g_hid[NMAX * 128];

__device__ __forceinline__ float ex2f(float x) {
    float r; asm("ex2.approx.f32 %0, %1;" : "=f"(r) : "f"(x)); return r;
}
__device__ __forceinline__ unsigned h2pack(float a, float b) {
    __half2 h = __floats2half2_rn(a, b);
    return *(unsigned*)&h;
}
__device__ __forceinline__ float2 h2unpack(unsigned u) {
    __half2 h = *(__half2*)&u;
    return __half22float2(h);
}
__device__ __forceinline__ u32 f2tf(float f) {
    u32 r; asm("cvt.rna.tf32.f32 %0, %1;" : "=r"(r) : "f"(f)); return r;
}
__device__ __forceinline__ void mma8(float* d, const u32* a, u32 b0, u32 b1) {
    asm volatile(
        "mma.sync.aligned.m16n8k8.row.col.f32.tf32.tf32.f32 "
        "{%0,%1,%2,%3}, {%4,%5,%6,%7}, {%8,%9}, {%0,%1,%2,%3};"
        : "+f"(d[0]), "+f"(d[1]), "+f"(d[2]), "+f"(d[3])
        : "r"(a[0]), "r"(a[1]), "r"(a[2]), "r"(a[3]), "r"(b0), "r"(b1));
}

// ---------------------------------------------------------------------------
// Edge preprocessing (unchanged from round 6)
// ---------------------------------------------------------------------------
__global__ void k_detect(const int* __restrict__ w, int E) {
    int lane = threadIdx.x;
    int bad = 0;
    int lim = min(128, E);
    for (int i = lane; i < lim; i += 32) bad |= w[2 * i + 1];
    unsigned b = __ballot_sync(0xffffffffu, bad != 0);
    if (lane == 0) g_is64 = (b == 0) ? 1 : 0;
}

__global__ void k_normcount(const void* __restrict__ raw, int E) {
    int base = (blockIdx.x * blockDim.x + threadIdx.x) * 4;
    if (base >= E) return;
    if (g_is64) {
        const long long* p = (const long long*)raw;
        #pragma unroll
        for (int j = 0; j < 4; j++) {
            int e = base + j;
            if (e < E) {
                int s = (int)p[e], d = (int)p[(size_t)E + e];
                g_edge[e] = make_int2(s, d);
                atomicAdd(&g_deg[d], 1);
            }
        }
    } else {
        const int* p = (const int*)raw;
        #pragma unroll
        for (int j = 0; j < 4; j++) {
            int e = base + j;
            if (e < E) {
                int s = p[e], d = p[(size_t)E + e];
                g_edge[e] = make_int2(s, d);
                atomicAdd(&g_deg[d], 1);
            }
        }
    }
}

__global__ void k_scan1(int n) {
    __shared__ int wsum[32];
    int tid = threadIdx.x;
    int i = blockIdx.x * 1024 + tid;
    int v = (i < n) ? g_deg[i] : 0;
    int lane = tid & 31, wid = tid >> 5;
    int s = v;
    #pragma unroll
    for (int o = 1; o < 32; o <<= 1) {
        int t = __shfl_up_sync(0xffffffffu, s, o);
        if (lane >= o) s += t;
    }
    if (lane == 31) wsum[wid] = s;
    __syncthreads();
    if (wid == 0) {
        int w = wsum[lane];
        #pragma unroll
        for (int o = 1; o < 32; o <<= 1) {
            int t = __shfl_up_sync(0xffffffffu, w, o);
            if (lane >= o) w += t;
        }
        wsum[lane] = w;
    }
    __syncthreads();
    int base = wid ? wsum[wid - 1] : 0;
    int excl = base + s - v;
    if (i < n) { g_off[i] = excl; g_cur[i] = excl; }
    if (tid == 1023) g_part[blockIdx.x] = base + s;
}

__global__ void k_scan2(int P) {
    __shared__ int s[64];
    int tid = threadIdx.x;
    s[tid] = (tid < P) ? g_part[tid] : 0;
    __syncthreads();
    if (tid == 0) {
        int acc = 0;
        for (int i = 0; i < P; i++) { int v = s[i]; s[i] = acc; acc += v; }
    }
    __syncthreads();
    if (tid < P) g_part[tid] = s[tid];
}

__global__ void k_scatter(int E) {
    int base = (blockIdx.x * blockDim.x + threadIdx.x) * 4;
    if (base >= E) return;
    #pragma unroll
    for (int j = 0; j < 4; j++) {
        int e = base + j;
        if (e < E) {
            int2 ed = g_edge[e];
            int pos = atomicAdd(&g_cur[ed.y], 1) + g_part[ed.y >> 10];
            g_ssrc[pos] = ed.x;
        }
    }
}

// ---------------------------------------------------------------------------
// Softmax aggregation, warp per destination node, fp16 gather (unchanged)
// ---------------------------------------------------------------------------
__global__ void k_aggr(const float* __restrict__ tp, int li,
                       float* __restrict__ so, int N) {
    int w = (blockIdx.x * blockDim.x + threadIdx.x) >> 5;
    int lane = threadIdx.x & 31;
    if (w >= N) return;
    float tl = __ldg(tp + li) * 1.4426950408889634f;
    int beg = g_off[w] + g_part[w >> 10];
    int dg = g_deg[w];
    float se0 = 0.f, se1 = 0.f, sn0 = 0.f, sn1 = 0.f;
    #pragma unroll 4
    for (int j = 0; j < dg; j++) {
        int s = __ldg(&g_ssrc[beg + j]);
        float2 v = h2unpack(__ldg(&g_zh[(size_t)s * 32 + lane]));
        float m0 = fmaxf(v.x, 0.f);
        float m1 = fmaxf(v.y, 0.f);
        float e0 = ex2f(m0 * tl);
        float e1 = ex2f(m1 * tl);
        se0 += e0; se1 += e1;
        sn0 = fmaf(m0, e0, sn0);
        sn1 = fmaf(m1, e1, sn1);
    }
    float2 zd = h2unpack(g_zh[(size_t)w * 32 + lane]);
    float2 o;
    o.x = zd.x + fmaf(1e-7f, se0, sn0) / (se0 + 1e-16f);
    o.y = zd.y + fmaf(1e-7f, se1, sn1) / (se1 + 1e-16f);
    ((float2*)so)[(size_t)w * 32 + lane] = o;
}

// ---------------------------------------------------------------------------
// gemmT: [N,128] @ [128,64] + bias (+residual, +LN epilogue, +head)  -- tf32 mma
// 128 threads / 4 warps. Tile 128 rows x 64 cols. Warp w: rows [w*32, w*32+32)
// = 2 m16-frags; 8 n8-frags; 16 k-steps of 8.
// modes: 0 encoder -> zh only; 1 -> h_out fp32 + zh = relu(LN);
//        2 -> z_out = relu(LN) fp32 + head tail
// smem: As 128x132 u32 (tf32, pad4 -> conflict-free frag LDS), Bp packed frags
// ---------------------------------------------------------------------------
#define GEMMT_SMEM ((128 * 132 + 8192 + 3 * 64 + 208) * 4)
__global__ __launch_bounds__(128) void k_gemmT(
    const float* __restrict__ A, const float* __restrict__ W,
    const float* __restrict__ bias, const float* __restrict__ lg,
    const float* __restrict__ lb, const float* __restrict__ lw,
    const float* __restrict__ lhb, float* __restrict__ h_out,
    float* __restrict__ z_out, int N, int addres, int mode) {
    extern __shared__ u32 smu[];
    u32*   Asu = smu;                       // 128*132
    u32*   Bp  = smu + 128 * 132;           // 16ks x 8nf x 32lane x 2
    float* bs  = (float*)(Bp + 8192);       // 64
    float* gs  = bs + 64;
    float* bb  = gs + 64;
    float* lws = bb + 64;                   // 208 (192 used)
    int tid = threadIdx.x;
    int r0 = blockIdx.x * 128;
    // stage A (row-major, tf32, padded stride 132)
    {
        const float4* a4 = (const float4*)A;
        uint4* s4 = (uint4*)Asu;
        #pragma unroll
        for (int i = 0; i < 32; i++) {
            int idx = tid + i * 128;                // 128 rows x 32 f4
            int row = min(r0 + (idx >> 5), N - 1);
            float4 v = __ldg(&a4[(size_t)row * 32 + (idx & 31)]);
            uint4 u; u.x = f2tf(v.x); u.y = f2tf(v.y); u.z = f2tf(v.z); u.w = f2tf(v.w);
            s4[(idx >> 5) * 33 + (idx & 31)] = u;
        }
    }
    // stage B packed fragments: id = (ks*8+nf)*32+lane
    {
        int lane = tid & 31;  (void)lane;
        uint2* Bp2 = (uint2*)Bp;
        #pragma unroll
        for (int i = 0; i < 32; i++) {
            int id = tid + i * 128;                 // 0..4095
            int ln = id & 31, nf = (id >> 5) & 7, ks = id >> 8;
            int g = ln >> 2, t = ln & 3;
            int k0 = ks * 8 + t, n = nf * 8 + g;
            uint2 b;
            b.x = f2tf(__ldg(&W[k0 * 64 + n]));
            b.y = f2tf(__ldg(&W[(k0 + 4) * 64 + n]));
            Bp2[id] = b;
        }
        if (tid < 64) {
            bs[tid] = bias[tid];
            if (mode) { gs[tid] = lg[tid]; bb[tid] = lb[tid]; }
        }
        if (mode == 2 && tid < 48) ((float4*)lws)[tid] = ((const float4*)lw)[tid];
    }
    __syncthreads();
    int warp = tid >> 5, lane = tid & 31;
    int g = lane >> 2, t = lane & 3;
    int wm = warp * 32;
    float acc[2][8][4];
    #pragma unroll
    for (int mf = 0; mf < 2; mf++)
        #pragma unroll
        for (int nf = 0; nf < 8; nf++)
            #pragma unroll
            for (int c = 0; c < 4; c++) acc[mf][nf][c] = 0.f;
    int baseA0 = (wm + g) * 132;
    int baseA1 = (wm + 16 + g) * 132;
    const uint2* Bp2 = (const uint2*)Bp;
    #pragma unroll
    for (int ks = 0; ks < 16; ks++) {
        int c0 = ks * 8 + t;
        u32 a[2][4];
        a[0][0] = Asu[baseA0 + c0];
        a[0][1] = Asu[baseA0 + 8 * 132 + c0];
        a[0][2] = Asu[baseA0 + c0 + 4];
        a[0][3] = Asu[baseA0 + 8 * 132 + c0 + 4];
        a[1][0] = Asu[baseA1 + c0];
        a[1][1] = Asu[baseA1 + 8 * 132 + c0];
        a[1][2] = Asu[baseA1 + c0 + 4];
        a[1][3] = Asu[baseA1 + 8 * 132 + c0 + 4];
        uint2 b[8];
        #pragma unroll
        for (int nf = 0; nf < 8; nf++) b[nf] = Bp2[(ks * 8 + nf) * 32 + lane];
        #pragma unroll
        for (int mf = 0; mf < 2; mf++)
            #pragma unroll
            for (int nf = 0; nf < 8; nf++)
                mma8(acc[mf][nf], a[mf], b[nf].x, b[nf].y);
    }
    // epilogue: thread owns rows {wm+16mf+g, +8}, cols {8nf+2t, +1}
    #pragma unroll
    for (int mf = 0; mf < 2; mf++) {
        #pragma unroll
        for (int rs = 0; rs < 2; rs++) {
            int rr = r0 + wm + mf * 16 + g + rs * 8;
            bool ok = rr < N;
            float y[16];
            #pragma unroll
            for (int nf = 0; nf < 8; nf++) {
                float2 bv = *(float2*)&bs[8 * nf + 2 * t];
                y[2 * nf]     = acc[mf][nf][rs * 2]     + bv.x;
                y[2 * nf + 1] = acc[mf][nf][rs * 2 + 1] + bv.y;
            }
            if (addres && ok) {
                #pragma unroll
                for (int nf = 0; nf < 8; nf++) {
                    float2 h = ((const float2*)h_out)[(size_t)rr * 32 + 4 * nf + t];
                    y[2 * nf] += h.x; y[2 * nf + 1] += h.y;
                }
            }
            if (mode == 0) {
                if (ok) {
                    #pragma unroll
                    for (int nf = 0; nf < 8; nf++)
                        g_zh[(size_t)rr * 32 + 4 * nf + t] = h2pack(y[2 * nf], y[2 * nf + 1]);
                }
                continue;
            }
            if (mode == 1 && ok) {
                #pragma unroll
                for (int nf = 0; nf < 8; nf++) {
                    float2 v; v.x = y[2 * nf]; v.y = y[2 * nf + 1];
                    ((float2*)h_out)[(size_t)rr * 32 + 4 * nf + t] = v;
                }
            }
            float s = 0.f, q = 0.f;
            #pragma unroll
            for (int c = 0; c < 16; c++) { s += y[c]; q = fmaf(y[c], y[c], q); }
            s += __shfl_xor_sync(0xffffffffu, s, 1);
            q += __shfl_xor_sync(0xffffffffu, q, 1);
            s += __shfl_xor_sync(0xffffffffu, s, 2);
            q += __shfl_xor_sync(0xffffffffu, q, 2);
            float mu = s * (1.f / 64.f);
            float var = q * (1.f / 64.f) - mu * mu;
            float rsv = rsqrtf(var + 1e-5f);
            float o16[16];
            #pragma unroll
            for (int nf = 0; nf < 8; nf++) {
                float2 gv = *(float2*)&gs[8 * nf + 2 * t];
                float2 cv = *(float2*)&bb[8 * nf + 2 * t];
                o16[2 * nf]     = fmaxf((y[2 * nf]     - mu) * rsv * gv.x + cv.x, 0.f);
                o16[2 * nf + 1] = fmaxf((y[2 * nf + 1] - mu) * rsv * gv.y + cv.y, 0.f);
            }
            if (mode == 1) {
                if (ok) {
                    #pragma unroll
                    for (int nf = 0; nf < 8; nf++)
                        g_zh[(size_t)rr * 32 + 4 * nf + t] = h2pack(o16[2 * nf], o16[2 * nf + 1]);
                }
            } else {  // mode 2: final out + head
                if (ok) {
                    #pragma unroll
                    for (int nf = 0; nf < 8; nf++) {
                        float2 v; v.x = o16[2 * nf]; v.y = o16[2 * nf + 1];
                        ((float2*)z_out)[(size_t)rr * 32 + 4 * nf + t] = v;
                    }
                }
                float p0 = 0.f, p1 = 0.f, p2 = 0.f;
                #pragma unroll
                for (int nf = 0; nf < 8; nf++) {
                    int c0 = 8 * nf + 2 * t, c1 = c0 + 1;
                    p0 = fmaf(o16[2 * nf], lws[c0 * 3 + 0], p0);
                    p1 = fmaf(o16[2 * nf], lws[c0 * 3 + 1], p1);
                    p2 = fmaf(o16[2 * nf], lws[c0 * 3 + 2], p2);
                    p0 = fmaf(o16[2 * nf + 1], lws[c1 * 3 + 0], p0);
                    p1 = fmaf(o16[2 * nf + 1], lws[c1 * 3 + 1], p1);
                    p2 = fmaf(o16[2 * nf + 1], lws[c1 * 3 + 2], p2);
                }
                p0 += __shfl_xor_sync(0xffffffffu, p0, 1);
                p1 += __shfl_xor_sync(0xffffffffu, p1, 1);
                p2 += __shfl_xor_sync(0xffffffffu, p2, 1);
                p0 += __shfl_xor_sync(0xffffffffu, p0, 2);
                p1 += __shfl_xor_sync(0xffffffffu, p1, 2);
                p2 += __shfl_xor_sync(0xffffffffu, p2, 2);
                if (t == 0 && ok) {
                    size_t base = (size_t)N * 64 + (size_t)rr * 3;
                    z_out[base + 0] = p0 + __ldg(lhb + 0);
                    z_out[base + 1] = p1 + __ldg(lhb + 1);
                    z_out[base + 2] = p2 + __ldg(lhb + 2);
                }
            }
        }
    }
}

// ---------------------------------------------------------------------------
// mlp1T: [N,64] @ [64,128] + bias -> LN(128) -> ReLU  -- tf32 mma
// 128 threads / 4 warps. Tile 64 rows x 128 cols. Warp w: rows [w*16, w*16+16)
// = 1 m16-frag; 16 n8-frags; 8 k-steps.
// ---------------------------------------------------------------------------
#define MLP1T_SMEM ((64 * 68 + 8192 + 3 * 128) * 4)
__global__ __launch_bounds__(128) void k_mlp1T(
    const float* __restrict__ A, const float* __restrict__ W,
    const float* __restrict__ bias, const float* __restrict__ lg,
    const float* __restrict__ lb, float* __restrict__ out, int N) {
    extern __shared__ u32 smu[];
    u32*   Asu = smu;                      // 64*68
    u32*   Bp  = smu + 64 * 68;            // 8ks x 16nf x 32 x 2
    float* bs  = (float*)(Bp + 8192);      // 128
    float* gs  = bs + 128;
    float* bb  = gs + 128;
    int tid = threadIdx.x;
    int r0 = blockIdx.x * 64;
    {
        const float4* a4 = (const float4*)A;
        uint4* s4 = (uint4*)Asu;
        #pragma unroll
        for (int i = 0; i < 8; i++) {
            int idx = tid + i * 128;                // 64 rows x 16 f4
            int row = min(r0 + (idx >> 4), N - 1);
            float4 v = __ldg(&a4[(size_t)row * 16 + (idx & 15)]);
            uint4 u; u.x = f2tf(v.x); u.y = f2tf(v.y); u.z = f2tf(v.z); u.w = f2tf(v.w);
            s4[(idx >> 4) * 17 + (idx & 15)] = u;
        }
        uint2* Bp2 = (uint2*)Bp;
        #pragma unroll
        for (int i = 0; i < 32; i++) {
            int id = tid + i * 128;                 // 0..4095
            int ln = id & 31, nf = (id >> 5) & 15, ks = id >> 9;
            int g = ln >> 2, t = ln & 3;
            int k0 = ks * 8 + t, n = nf * 8 + g;
            uint2 b;
            b.x = f2tf(__ldg(&W[k0 * 128 + n]));
            b.y = f2tf(__ldg(&W[(k0 + 4) * 128 + n]));
            Bp2[id] = b;
        }
        if (tid < 128) { bs[tid] = bias[tid]; gs[tid] = lg[tid]; bb[tid] = lb[tid]; }
    }
    __syncthreads();
    int warp = tid >> 5, lane = tid & 31;
    int g = lane >> 2, t = lane & 3;
    int wm = warp * 16;
    float acc[16][4];
    #pragma unroll
    for (int nf = 0; nf < 16; nf++)
        #pragma unroll
        for (int c = 0; c < 4; c++) acc[nf][c] = 0.f;
    int baseA = (wm + g) * 68;
    const uint2* Bp2 = (const uint2*)Bp;
    #pragma unroll
    for (int ks = 0; ks < 8; ks++) {
        int c0 = ks * 8 + t;
        u32 a[4];
        a[0] = Asu[baseA + c0];
        a[1] = Asu[baseA + 8 * 68 + c0];
        a[2] = Asu[baseA + c0 + 4];
        a[3] = Asu[baseA + 8 * 68 + c0 + 4];
        #pragma unroll
        for (int nf = 0; nf < 16; nf++) {
            uint2 b = Bp2[(ks * 16 + nf) * 32 + lane];
            mma8(acc[nf], a, b.x, b.y);
        }
    }
    #pragma unroll
    for (int rs = 0; rs < 2; rs++) {
        int rr = r0 + wm + g + rs * 8;
        float y[32];
        #pragma unroll
        for (int nf = 0; nf < 16; nf++) {
            float2 bv = *(float2*)&bs[8 * nf + 2 * t];
            y[2 * nf]     = acc[nf][rs * 2]     + bv.x;
            y[2 * nf + 1] = acc[nf][rs * 2 + 1] + bv.y;
        }
        float s = 0.f, q = 0.f;
        #pragma unroll
        for (int c = 0; c < 32; c++) { s += y[c]; q = fmaf(y[c], y[c], q); }
        s += __shfl_xor_sync(0xffffffffu, s, 1);
        q += __shfl_xor_sync(0xffffffffu, q, 1);
        s += __shfl_xor_sync(0xffffffffu, s, 2);
        q += __shfl_xor_sync(0xffffffffu, q, 2);
        float mu = s * (1.f / 128.f);
        float var = q * (1.f / 128.f) - mu * mu;
        float rsv = rsqrtf(var + 1e-5f);
        if (rr < N) {
            #pragma unroll
            for (int nf = 0; nf < 16; nf++) {
                float2 gv = *(float2*)&gs[8 * nf + 2 * t];
                float2 cv = *(float2*)&bb[8 * nf + 2 * t];
                float2 v;
                v.x = fmaxf((y[2 * nf]     - mu) * rsv * gv.x + cv.x, 0.f);
                v.y = fmaxf((y[2 * nf + 1] - mu) * rsv * gv.y + cv.y, 0.f);
                ((float2*)out)[(size_t)rr * 64 + 4 * nf + t] = v;
            }
        }
    }
}

// ---------------------------------------------------------------------------
// Host launch
// ---------------------------------------------------------------------------
extern "C" void kernel_launch(void* const* d_in, const int* in_sizes, int n_in,
                              void* d_out, int out_size) {
    const float* x    = (const float*)d_in[0];
    const void*  ei   = d_in[1];
    const float* encW = (const float*)d_in[2];
    const float* encB = (const float*)d_in[3];
    const float* t    = (const float*)d_in[4];
    const float* W1   = (const float*)d_in[5];
    const float* b1   = (const float*)d_in[6];
    const float* g1   = (const float*)d_in[7];
    const float* bb1  = (const float*)d_in[8];
    const float* W2   = (const float*)d_in[9];
    const float* b2   = (const float*)d_in[10];
    const float* ng   = (const float*)d_in[11];
    const float* nb   = (const float*)d_in[12];
    const float* lw   = (const float*)d_in[13];
    const float* lb   = (const float*)d_in[14];
    int N = in_sizes[0] / 128;
    int E = in_sizes[1] / 2;
    if (N > NMAX) N = NMAX;
    if (E > EMAX) E = EMAX;
    float* out = (float*)d_out;

    cudaFuncSetAttribute(k_mlp1T, cudaFuncAttributeMaxDynamicSharedMemorySize, MLP1T_SMEM);
    cudaFuncSetAttribute(k_gemmT, cudaFuncAttributeMaxDynamicSharedMemorySize, GEMMT_SMEM);

    float *gh, *gsv, *ghid;
    int *gdeg;
    cudaGetSymbolAddress((void**)&gh,   g_h);
    cudaGetSymbolAddress((void**)&gsv,  g_s);
    cudaGetSymbolAddress((void**)&ghid, g_hid);
    cudaGetSymbolAddress((void**)&gdeg, g_deg);

    int eb4     = (E + 1023) / 1024;
    int rowsW   = (N + 7) / 8;
    int tiles64 = (N + 63) / 64;
    int tilesB  = (N + 127) / 128;
    int sblocks = (N + 1023) / 1024;

    // edge preprocessing (CSR by dst)
    cudaMemsetAsync(gdeg, 0, (size_t)N * sizeof(int));
    k_detect<<<1, 32>>>((const int*)ei, E);
    k_normcount<<<eb4, 256>>>(ei, E);
    k_scan1<<<sblocks, 1024>>>(N);
    k_scan2<<<1, 64>>>(sblocks);
    k_scatter<<<eb4, 256>>>(E);

    // encoder: x @ encW + encB -> zh (mode 0)
    k_gemmT<<<tilesB, 128, GEMMT_SMEM>>>(x, encW, encB, nullptr, nullptr,
                                         nullptr, nullptr, gh, nullptr, N, 0, 0);

    for (int i = 0; i < 3; i++) {
        k_aggr<<<rowsW, 256>>>(t, i, gsv, N);
        k_mlp1T<<<tiles64, 128, MLP1T_SMEM>>>(gsv, W1 + i * 8192, b1 + i * 128,
                                              g1 + i * 128, bb1 + i * 128, ghid, N);
        if (i < 2) {
            // mlp2 (+res if i>0) -> gh fp32; zh = relu(LN(gh, ng[i+1]))
            k_gemmT<<<tilesB, 128, GEMMT_SMEM>>>(ghid, W2 + i * 8192, b2 + i * 64,
                                                 ng + (i + 1) * 64, nb + (i + 1) * 64,
                                                 nullptr, nullptr, gh, nullptr,
                                                 N, i ? 1 : 0, 1);
        } else {
            // last: res + final LN(ng[0]) + ReLU -> out, head -> out tail
            k_gemmT<<<tilesB, 128, GEMMT_SMEM>>>(ghid, W2 + i * 8192, b2 + i * 64,
                                                 ng, nb, lw, lb, gh, out, N, 1, 2);
        }
    }
}

// round 8
// speedup vs baseline: 1.9636x; 1.0147x over previous
#include <cuda_runtime.h>
#include <cuda_fp16.h>

// ---------------------------------------------------------------------------
// DeeperGCN round 8:
//  - GEMMs: fp16 split (hi+lo, 22-bit) m16n8k16 mma, 3 MMAs per k16 ->
//    ~fp32-grade GEMM error (~1e-6/GEMM) at tensor-pipe speed
//  - dtype detect folded into normcount; scan2 folded into scan1 (last-block)
//  - fp16 edge gather + MUFU exp aggregation unchanged
// ---------------------------------------------------------------------------

#define NMAX 50048
#define EMAX 800000
typedef unsigned long long u64;
typedef unsigned int u32;

__device__ int2     g_edge[EMAX];
__device__ int      g_ssrc[EMAX];
__device__ int      g_deg[NMAX];
__device__ int      g_off[NMAX];
__device__ int      g_cur[NMAX];
__device__ int      g_part[64];
__device__ int      g_scan_done;
__device__ unsigned g_zh [NMAX * 32];     // half2 per entry (64 feats / row)
__device__ float    g_h  [NMAX * 64];
__device__ float    g_s  [NMAX * 64];
__device__ float    g_hid[NMAX * 128];

__device__ __forceinline__ float ex2f(float x) {
    float r; asm("ex2.approx.f32 %0, %1;" : "=f"(r) : "f"(x)); return r;
}
__device__ __forceinline__ unsigned h2pack(float a, float b) {
    __half2 h = __floats2half2_rn(a, b);
    return *(unsigned*)&h;
}
__device__ __forceinline__ float2 h2unpack(unsigned u) {
    __half2 h = *(__half2*)&u;
    return __half22float2(h);
}
// split a pair of floats into fp16 hi + fp16 lo packs
__device__ __forceinline__ void hsplit(float a, float b, u32 &hi, u32 &lo) {
    hi = h2pack(a, b);
    float2 f = h2unpack(hi);
    lo = h2pack(a - f.x, b - f.y);
}
__device__ __forceinline__ void mmah(float* d, const u32* a, u32 b0, u32 b1) {
    asm volatile(
        "mma.sync.aligned.m16n8k16.row.col.f32.f16.f16.f32 "
        "{%0,%1,%2,%3}, {%4,%5,%6,%7}, {%8,%9}, {%0,%1,%2,%3};"
        : "+f"(d[0]), "+f"(d[1]), "+f"(d[2]), "+f"(d[3])
        : "r"(a[0]), "r"(a[1]), "r"(a[2]), "r"(a[3]), "r"(b0), "r"(b1));
}

// ---------------------------------------------------------------------------
// Edge preprocessing: normcount (with inline dtype detect), fused scan, scatter
// ---------------------------------------------------------------------------
__global__ void k_normcount(const void* __restrict__ raw, int E) {
    __shared__ int s_is64;
    int tid = threadIdx.x;
    if (tid < 32) {
        const int* w = (const int*)raw;
        int bad = 0;
        int lim = min(128, E);
        for (int i = tid; i < lim; i += 32) bad |= w[2 * i + 1];
        unsigned b = __ballot_sync(0xffffffffu, bad != 0);
        if (tid == 0) s_is64 = (b == 0) ? 1 : 0;
    }
    if (blockIdx.x == 0 && tid == 0) g_scan_done = 0;
    __syncthreads();
    int is64 = s_is64;
    int base = (blockIdx.x * blockDim.x + tid) * 4;
    if (base >= E) return;
    if (is64) {
        const long long* p = (const long long*)raw;
        #pragma unroll
        for (int j = 0; j < 4; j++) {
            int e = base + j;
            if (e < E) {
                int s = (int)p[e], d = (int)p[(size_t)E + e];
                g_edge[e] = make_int2(s, d);
                atomicAdd(&g_deg[d], 1);
            }
        }
    } else {
        const int* p = (const int*)raw;
        #pragma unroll
        for (int j = 0; j < 4; j++) {
            int e = base + j;
            if (e < E) {
                int s = p[e], d = p[(size_t)E + e];
                g_edge[e] = make_int2(s, d);
                atomicAdd(&g_deg[d], 1);
            }
        }
    }
}

// per-1024-block scan; LAST block to finish scans the block partials
__global__ void k_scan(int n) {
    __shared__ int wsum[32];
    __shared__ int amLast;
    __shared__ int pp[64];
    int tid = threadIdx.x;
    int i = blockIdx.x * 1024 + tid;
    int v = (i < n) ? g_deg[i] : 0;
    int lane = tid & 31, wid = tid >> 5;
    int s = v;
    #pragma unroll
    for (int o = 1; o < 32; o <<= 1) {
        int t = __shfl_up_sync(0xffffffffu, s, o);
        if (lane >= o) s += t;
    }
    if (lane == 31) wsum[wid] = s;
    __syncthreads();
    if (wid == 0) {
        int w = wsum[lane];
        #pragma unroll
        for (int o = 1; o < 32; o <<= 1) {
            int t = __shfl_up_sync(0xffffffffu, w, o);
            if (lane >= o) w += t;
        }
        wsum[lane] = w;
    }
    __syncthreads();
    int base = wid ? wsum[wid - 1] : 0;
    int excl = base + s - v;
    if (i < n) { g_off[i] = excl; g_cur[i] = excl; }
    if (tid == 1023) {
        g_part[blockIdx.x] = base + s;
        __threadfence();
        int t = atomicAdd(&g_scan_done, 1);
        amLast = (t == (int)gridDim.x - 1);
    }
    __syncthreads();
    if (amLast) {
        int P = gridDim.x;
        if (tid < 64) pp[tid] = (tid < P) ? g_part[tid] : 0;
        __syncthreads();
        if (tid == 0) {
            int acc = 0;
            for (int k = 0; k < P; k++) { int vv = pp[k]; pp[k] = acc; acc += vv; }
        }
        __syncthreads();
        if (tid < P) g_part[tid] = pp[tid];
    }
}

__global__ void k_scatter(int E) {
    int base = (blockIdx.x * blockDim.x + threadIdx.x) * 4;
    if (base >= E) return;
    #pragma unroll
    for (int j = 0; j < 4; j++) {
        int e = base + j;
        if (e < E) {
            int2 ed = g_edge[e];
            int pos = atomicAdd(&g_cur[ed.y], 1) + g_part[ed.y >> 10];
            g_ssrc[pos] = ed.x;
        }
    }
}

// ---------------------------------------------------------------------------
// Softmax aggregation, warp per destination node, fp16 gather (unchanged)
// ---------------------------------------------------------------------------
__global__ void k_aggr(const float* __restrict__ tp, int li,
                       float* __restrict__ so, int N) {
    int w = (blockIdx.x * blockDim.x + threadIdx.x) >> 5;
    int lane = threadIdx.x & 31;
    if (w >= N) return;
    float tl = __ldg(tp + li) * 1.4426950408889634f;
    int beg = g_off[w] + g_part[w >> 10];
    int dg = g_deg[w];
    float se0 = 0.f, se1 = 0.f, sn0 = 0.f, sn1 = 0.f;
    #pragma unroll 4
    for (int j = 0; j < dg; j++) {
        int s = __ldg(&g_ssrc[beg + j]);
        float2 v = h2unpack(__ldg(&g_zh[(size_t)s * 32 + lane]));
        float m0 = fmaxf(v.x, 0.f);
        float m1 = fmaxf(v.y, 0.f);
        float e0 = ex2f(m0 * tl);
        float e1 = ex2f(m1 * tl);
        se0 += e0; se1 += e1;
        sn0 = fmaf(m0, e0, sn0);
        sn1 = fmaf(m1, e1, sn1);
    }
    float2 zd = h2unpack(g_zh[(size_t)w * 32 + lane]);
    float2 o;
    o.x = zd.x + fmaf(1e-7f, se0, sn0) / (se0 + 1e-16f);
    o.y = zd.y + fmaf(1e-7f, se1, sn1) / (se1 + 1e-16f);
    ((float2*)so)[(size_t)w * 32 + lane] = o;
}

// ---------------------------------------------------------------------------
// gemmT: [N,128] @ [128,64] + bias (+residual, +LN epilogue, +head)
// fp16-split m16n8k16. 128 thr / 4 warps; tile 128 rows x 64 cols;
// warp w: rows [w*32, w*32+32) (2 m-frags), 8 n-frags, 8 k-steps of 16.
// A smem: hi/lo u32 pair arrays [128][68] (kpairs, pad4 -> conflict-free)
// B smem: fragment-packed uint2 [8ks][8nf][32lane], hi and lo
// modes: 0 encoder -> zh only; 1 -> h fp32 + zh = relu(LN); 2 -> out + head
// ---------------------------------------------------------------------------
#define GEMMT_U32 (2 * 128 * 68 + 2 * 4096 + 400)
#define GEMMT_SMEM (GEMMT_U32 * 4)
__global__ __launch_bounds__(128) void k_gemmT(
    const float* __restrict__ A, const float* __restrict__ W,
    const float* __restrict__ bias, const float* __restrict__ lg,
    const float* __restrict__ lb, const float* __restrict__ lw,
    const float* __restrict__ lhb, float* __restrict__ h_out,
    float* __restrict__ z_out, int N, int addres, int mode) {
    extern __shared__ u32 smu[];
    u32*   Ah  = smu;                       // 128*68
    u32*   Al  = Ah + 128 * 68;             // 128*68
    uint2* Bh  = (uint2*)(Al + 128 * 68);   // 2048 uint2
    uint2* Bl  = Bh + 2048;                 // 2048 uint2
    float* bs  = (float*)(Bl + 2048);       // 64
    float* gs  = bs + 64;
    float* bb  = gs + 64;
    float* lws = bb + 64;                   // 208 (192 used)
    int tid = threadIdx.x;
    int r0 = blockIdx.x * 128;
    // stage A: hi/lo fp16 pairs, row-major kpairs, stride 68
    {
        const float4* a4 = (const float4*)A;
        #pragma unroll
        for (int i = 0; i < 32; i++) {
            int idx = tid + i * 128;                // 128 rows x 32 f4
            int row = idx >> 5, c = idx & 31;
            int grow = min(r0 + row, N - 1);
            float4 v = __ldg(&a4[(size_t)grow * 32 + c]);
            u32 h0, l0, h1, l1;
            hsplit(v.x, v.y, h0, l0);
            hsplit(v.z, v.w, h1, l1);
            *(uint2*)&Ah[row * 68 + 2 * c] = make_uint2(h0, h1);
            *(uint2*)&Al[row * 68 + 2 * c] = make_uint2(l0, l1);
        }
    }
    // stage B fragments: id = (ks*8+nf)*32 + lane
    {
        #pragma unroll
        for (int i = 0; i < 16; i++) {
            int id = tid + i * 128;                 // 0..2047
            int ln = id & 31, nf = (id >> 5) & 7, ks = id >> 8;
            int g = ln >> 2, t = ln & 3;
            int n = nf * 8 + g, k0 = ks * 16 + 2 * t;
            float w00 = __ldg(&W[(k0)     * 64 + n]);
            float w01 = __ldg(&W[(k0 + 1) * 64 + n]);
            float w10 = __ldg(&W[(k0 + 8) * 64 + n]);
            float w11 = __ldg(&W[(k0 + 9) * 64 + n]);
            u32 bh0, bl0, bh1, bl1;
            hsplit(w00, w01, bh0, bl0);
            hsplit(w10, w11, bh1, bl1);
            Bh[id] = make_uint2(bh0, bh1);
            Bl[id] = make_uint2(bl0, bl1);
        }
        if (tid < 64) {
            bs[tid] = bias[tid];
            if (mode) { gs[tid] = lg[tid]; bb[tid] = lb[tid]; }
        }
        if (mode == 2 && tid < 48) ((float4*)lws)[tid] = ((const float4*)lw)[tid];
    }
    __syncthreads();
    int warp = tid >> 5, lane = tid & 31;
    int g = lane >> 2, t = lane & 3;
    int wm = warp * 32;
    float acc[2][8][4];
    #pragma unroll
    for (int mf = 0; mf < 2; mf++)
        #pragma unroll
        for (int nf = 0; nf < 8; nf++)
            #pragma unroll
            for (int c = 0; c < 4; c++) acc[mf][nf][c] = 0.f;
    #pragma unroll
    for (int ks = 0; ks < 8; ks++) {
        int kp = ks * 8 + t;
        u32 ah[2][4], al[2][4];
        #pragma unroll
        for (int mf = 0; mf < 2; mf++) {
            int b0 = (wm + mf * 16 + g) * 68;
            int b1 = (wm + mf * 16 + 8 + g) * 68;
            ah[mf][0] = Ah[b0 + kp];     ah[mf][1] = Ah[b1 + kp];
            ah[mf][2] = Ah[b0 + kp + 4]; ah[mf][3] = Ah[b1 + kp + 4];
            al[mf][0] = Al[b0 + kp];     al[mf][1] = Al[b1 + kp];
            al[mf][2] = Al[b0 + kp + 4]; al[mf][3] = Al[b1 + kp + 4];
        }
        #pragma unroll
        for (int nf = 0; nf < 8; nf++) {
            uint2 bh = Bh[(ks * 8 + nf) * 32 + lane];
            uint2 bl = Bl[(ks * 8 + nf) * 32 + lane];
            #pragma unroll
            for (int mf = 0; mf < 2; mf++) {
                mmah(acc[mf][nf], ah[mf], bl.x, bl.y);   // Ahi*Blo
                mmah(acc[mf][nf], al[mf], bh.x, bh.y);   // Alo*Bhi
                mmah(acc[mf][nf], ah[mf], bh.x, bh.y);   // Ahi*Bhi
            }
        }
    }
    // epilogue: thread owns rows {wm+16mf+g, +8}, cols {8nf+2t, +1}
    #pragma unroll
    for (int mf = 0; mf < 2; mf++) {
        #pragma unroll
        for (int rs = 0; rs < 2; rs++) {
            int rr = r0 + wm + mf * 16 + g + rs * 8;
            bool ok = rr < N;
            float y[16];
            #pragma unroll
            for (int nf = 0; nf < 8; nf++) {
                float2 bv = *(float2*)&bs[8 * nf + 2 * t];
                y[2 * nf]     = acc[mf][nf][rs * 2]     + bv.x;
                y[2 * nf + 1] = acc[mf][nf][rs * 2 + 1] + bv.y;
            }
            if (addres && ok) {
                #pragma unroll
                for (int nf = 0; nf < 8; nf++) {
                    float2 h = ((const float2*)h_out)[(size_t)rr * 32 + 4 * nf + t];
                    y[2 * nf] += h.x; y[2 * nf + 1] += h.y;
                }
            }
            if (mode == 0) {
                if (ok) {
                    #pragma unroll
                    for (int nf = 0; nf < 8; nf++)
                        g_zh[(size_t)rr * 32 + 4 * nf + t] = h2pack(y[2 * nf], y[2 * nf + 1]);
                }
                continue;
            }
            if (mode == 1 && ok) {
                #pragma unroll
                for (int nf = 0; nf < 8; nf++) {
                    float2 v; v.x = y[2 * nf]; v.y = y[2 * nf + 1];
                    ((float2*)h_out)[(size_t)rr * 32 + 4 * nf + t] = v;
                }
            }
            float s = 0.f, q = 0.f;
            #pragma unroll
            for (int c = 0; c < 16; c++) { s += y[c]; q = fmaf(y[c], y[c], q); }
            s += __shfl_xor_sync(0xffffffffu, s, 1);
            q += __shfl_xor_sync(0xffffffffu, q, 1);
            s += __shfl_xor_sync(0xffffffffu, s, 2);
            q += __shfl_xor_sync(0xffffffffu, q, 2);
            float mu = s * (1.f / 64.f);
            float var = q * (1.f / 64.f) - mu * mu;
            float rsv = rsqrtf(var + 1e-5f);
            float o16[16];
            #pragma unroll
            for (int nf = 0; nf < 8; nf++) {
                float2 gv = *(float2*)&gs[8 * nf + 2 * t];
                float2 cv = *(float2*)&bb[8 * nf + 2 * t];
                o16[2 * nf]     = fmaxf((y[2 * nf]     - mu) * rsv * gv.x + cv.x, 0.f);
                o16[2 * nf + 1] = fmaxf((y[2 * nf + 1] - mu) * rsv * gv.y + cv.y, 0.f);
            }
            if (mode == 1) {
                if (ok) {
                    #pragma unroll
                    for (int nf = 0; nf < 8; nf++)
                        g_zh[(size_t)rr * 32 + 4 * nf + t] = h2pack(o16[2 * nf], o16[2 * nf + 1]);
                }
            } else {  // mode 2: final out + head
                if (ok) {
                    #pragma unroll
                    for (int nf = 0; nf < 8; nf++) {
                        float2 v; v.x = o16[2 * nf]; v.y = o16[2 * nf + 1];
                        ((float2*)z_out)[(size_t)rr * 32 + 4 * nf + t] = v;
                    }
                }
                float p0 = 0.f, p1 = 0.f, p2 = 0.f;
                #pragma unroll
                for (int nf = 0; nf < 8; nf++) {
                    int c0 = 8 * nf + 2 * t, c1 = c0 + 1;
                    p0 = fmaf(o16[2 * nf], lws[c0 * 3 + 0], p0);
                    p1 = fmaf(o16[2 * nf], lws[c0 * 3 + 1], p1);
                    p2 = fmaf(o16[2 * nf], lws[c0 * 3 + 2], p2);
                    p0 = fmaf(o16[2 * nf + 1], lws[c1 * 3 + 0], p0);
                    p1 = fmaf(o16[2 * nf + 1], lws[c1 * 3 + 1], p1);
                    p2 = fmaf(o16[2 * nf + 1], lws[c1 * 3 + 2], p2);
                }
                p0 += __shfl_xor_sync(0xffffffffu, p0, 1);
                p1 += __shfl_xor_sync(0xffffffffu, p1, 1);
                p2 += __shfl_xor_sync(0xffffffffu, p2, 1);
                p0 += __shfl_xor_sync(0xffffffffu, p0, 2);
                p1 += __shfl_xor_sync(0xffffffffu, p1, 2);
                p2 += __shfl_xor_sync(0xffffffffu, p2, 2);
                if (t == 0 && ok) {
                    size_t base = (size_t)N * 64 + (size_t)rr * 3;
                    z_out[base + 0] = p0 + __ldg(lhb + 0);
                    z_out[base + 1] = p1 + __ldg(lhb + 1);
                    z_out[base + 2] = p2 + __ldg(lhb + 2);
                }
            }
        }
    }
}

// ---------------------------------------------------------------------------
// mlp1T: [N,64] @ [64,128] + bias -> LN(128) -> ReLU   fp16-split m16n8k16
// 128 thr / 4 warps; tile 64 rows x 128 cols; warp: 1 m-frag, 16 nf, 4 ksteps
// A hi/lo [64][36]; B frags [4ks][16nf][32lane] uint2 hi/lo
// ---------------------------------------------------------------------------
#define MLP1T_U32 (2 * 64 * 36 + 2 * 4096 + 384)
#define MLP1T_SMEM (MLP1T_U32 * 4)
__global__ __launch_bounds__(128) void k_mlp1T(
    const float* __restrict__ A, const float* __restrict__ W,
    const float* __restrict__ bias, const float* __restrict__ lg,
    const float* __restrict__ lb, float* __restrict__ out, int N) {
    extern __shared__ u32 smu[];
    u32*   Ah = smu;                        // 64*36
    u32*   Al = Ah + 64 * 36;
    uint2* Bh = (uint2*)(Al + 64 * 36);     // 2048 uint2
    uint2* Bl = Bh + 2048;
    float* bs = (float*)(Bl + 2048);        // 128
    float* gs = bs + 128;
    float* bb = gs + 128;
    int tid = threadIdx.x;
    int r0 = blockIdx.x * 64;
    {
        const float4* a4 = (const float4*)A;
        #pragma unroll
        for (int i = 0; i < 8; i++) {
            int idx = tid + i * 128;                // 64 rows x 16 f4
            int row = idx >> 4, c = idx & 15;
            int grow = min(r0 + row, N - 1);
            float4 v = __ldg(&a4[(size_t)grow * 16 + c]);
            u32 h0, l0, h1, l1;
            hsplit(v.x, v.y, h0, l0);
            hsplit(v.z, v.w, h1, l1);
            *(uint2*)&Ah[row * 36 + 2 * c] = make_uint2(h0, h1);
            *(uint2*)&Al[row * 36 + 2 * c] = make_uint2(l0, l1);
        }
        #pragma unroll
        for (int i = 0; i < 16; i++) {
            int id = tid + i * 128;                 // 0..2047
            int ln = id & 31, nf = (id >> 5) & 15, ks = id >> 9;
            int g = ln >> 2, t = ln & 3;
            int n = nf * 8 + g, k0 = ks * 16 + 2 * t;
            float w00 = __ldg(&W[(k0)     * 128 + n]);
            float w01 = __ldg(&W[(k0 + 1) * 128 + n]);
            float w10 = __ldg(&W[(k0 + 8) * 128 + n]);
            float w11 = __ldg(&W[(k0 + 9) * 128 + n]);
            u32 bh0, bl0, bh1, bl1;
            hsplit(w00, w01, bh0, bl0);
            hsplit(w10, w11, bh1, bl1);
            Bh[id] = make_uint2(bh0, bh1);
            Bl[id] = make_uint2(bl0, bl1);
        }
        if (tid < 128) { bs[tid] = bias[tid]; gs[tid] = lg[tid]; bb[tid] = lb[tid]; }
    }
    __syncthreads();
    int warp = tid >> 5, lane = tid & 31;
    int g = lane >> 2, t = lane & 3;
    int wm = warp * 16;
    float acc[16][4];
    #pragma unroll
    for (int nf = 0; nf < 16; nf++)
        #pragma unroll
        for (int c = 0; c < 4; c++) acc[nf][c] = 0.f;
    #pragma unroll
    for (int ks = 0; ks < 4; ks++) {
        int kp = ks * 8 + t;
        int b0 = (wm + g) * 36, b1 = (wm + 8 + g) * 36;
        u32 ah[4], al[4];
        ah[0] = Ah[b0 + kp];     ah[1] = Ah[b1 + kp];
        ah[2] = Ah[b0 + kp + 4]; ah[3] = Ah[b1 + kp + 4];
        al[0] = Al[b0 + kp];     al[1] = Al[b1 + kp];
        al[2] = Al[b0 + kp + 4]; al[3] = Al[b1 + kp + 4];
        #pragma unroll
        for (int nf = 0; nf < 16; nf++) {
            uint2 bh = Bh[(ks * 16 + nf) * 32 + lane];
            uint2 bl = Bl[(ks * 16 + nf) * 32 + lane];
            mmah(acc[nf], ah, bl.x, bl.y);
            mmah(acc[nf], al, bh.x, bh.y);
            mmah(acc[nf], ah, bh.x, bh.y);
        }
    }
    #pragma unroll
    for (int rs = 0; rs < 2; rs++) {
        int rr = r0 + wm + g + rs * 8;
        float y[32];
        #pragma unroll
        for (int nf = 0; nf < 16; nf++) {
            float2 bv = *(float2*)&bs[8 * nf + 2 * t];
            y[2 * nf]     = acc[nf][rs * 2]     + bv.x;
            y[2 * nf + 1] = acc[nf][rs * 2 + 1] + bv.y;
        }
        float s = 0.f, q = 0.f;
        #pragma unroll
        for (int c = 0; c < 32; c++) { s += y[c]; q = fmaf(y[c], y[c], q); }
        s += __shfl_xor_sync(0xffffffffu, s, 1);
        q += __shfl_xor_sync(0xffffffffu, q, 1);
        s += __shfl_xor_sync(0xffffffffu, s, 2);
        q += __shfl_xor_sync(0xffffffffu, q, 2);
        float mu = s * (1.f / 128.f);
        float var = q * (1.f / 128.f) - mu * mu;
        float rsv = rsqrtf(var + 1e-5f);
        if (rr < N) {
            #pragma unroll
            for (int nf = 0; nf < 16; nf++) {
                float2 gv = *(float2*)&gs[8 * nf + 2 * t];
                float2 cv = *(float2*)&bb[8 * nf + 2 * t];
                float2 v;
                v.x = fmaxf((y[2 * nf]     - mu) * rsv * gv.x + cv.x, 0.f);
                v.y = fmaxf((y[2 * nf + 1] - mu) * rsv * gv.y + cv.y, 0.f);
                ((float2*)out)[(size_t)rr * 64 + 4 * nf + t] = v;
            }
        }
    }
}

// ---------------------------------------------------------------------------
// Host launch
// ---------------------------------------------------------------------------
extern "C" void kernel_launch(void* const* d_in, const int* in_sizes, int n_in,
                              void* d_out, int out_size) {
    const float* x    = (const float*)d_in[0];
    const void*  ei   = d_in[1];
    const float* encW = (const float*)d_in[2];
    const float* encB = (const float*)d_in[3];
    const float* t    = (const float*)d_in[4];
    const float* W1   = (const float*)d_in[5];
    const float* b1   = (const float*)d_in[6];
    const float* g1   = (const float*)d_in[7];
    const float* bb1  = (const float*)d_in[8];
    const float* W2   = (const float*)d_in[9];
    const float* b2   = (const float*)d_in[10];
    const float* ng   = (const float*)d_in[11];
    const float* nb   = (const float*)d_in[12];
    const float* lw   = (const float*)d_in[13];
    const float* lb   = (const float*)d_in[14];
    int N = in_sizes[0] / 128;
    int E = in_sizes[1] / 2;
    if (N > NMAX) N = NMAX;
    if (E > EMAX) E = EMAX;
    float* out = (float*)d_out;

    cudaFuncSetAttribute(k_mlp1T, cudaFuncAttributeMaxDynamicSharedMemorySize, MLP1T_SMEM);
    cudaFuncSetAttribute(k_gemmT, cudaFuncAttributeMaxDynamicSharedMemorySize, GEMMT_SMEM);

    float *gh, *gsv, *ghid;
    int *gdeg;
    cudaGetSymbolAddress((void**)&gh,   g_h);
    cudaGetSymbolAddress((void**)&gsv,  g_s);
    cudaGetSymbolAddress((void**)&ghid, g_hid);
    cudaGetSymbolAddress((void**)&gdeg, g_deg);

    int eb4     = (E + 1023) / 1024;
    int rowsW   = (N + 7) / 8;
    int tiles64 = (N + 63) / 64;
    int tilesB  = (N + 127) / 128;
    int sblocks = (N + 1023) / 1024;

    // edge preprocessing (CSR by dst)
    cudaMemsetAsync(gdeg, 0, (size_t)N * sizeof(int));
    k_normcount<<<eb4, 256>>>(ei, E);
    k_scan<<<sblocks, 1024>>>(N);
    k_scatter<<<eb4, 256>>>(E);

    // encoder: x @ encW + encB -> zh (mode 0)
    k_gemmT<<<tilesB, 128, GEMMT_SMEM>>>(x, encW, encB, nullptr, nullptr,
                                         nullptr, nullptr, gh, nullptr, N, 0, 0);

    for (int i = 0; i < 3; i++) {
        k_aggr<<<rowsW, 256>>>(t, i, gsv, N);
        k_mlp1T<<<tiles64, 128, MLP1T_SMEM>>>(gsv, W1 + i * 8192, b1 + i * 128,
                                              g1 + i * 128, bb1 + i * 128, ghid, N);
        if (i < 2) {
            // mlp2 (+res if i>0) -> gh fp32; zh = relu(LN(gh, ng[i+1]))
            k_gemmT<<<tilesB, 128, GEMMT_SMEM>>>(ghid, W2 + i * 8192, b2 + i * 64,
                                                 ng + (i + 1) * 64, nb + (i + 1) * 64,
                                                 nullptr, nullptr, gh, nullptr,
                                                 N, i ? 1 : 0, 1);
        } else {
            // last: res + final LN(ng[0]) + ReLU -> out, head -> out tail
            k_gemmT<<<tilesB, 128, GEMMT_SMEM>>>(ghid, W2 + i * 8192, b2 + i * 64,
                                                 ng, nb, lw, lb, gh, out, N, 1, 2);
        }
    }
}

// round 9
// speedup vs baseline: 2.0740x; 1.0562x over previous
#include <cuda_runtime.h>
#include <cuda_fp16.h>

// ---------------------------------------------------------------------------
// DeeperGCN round 9:
//  - gemmT: 256 thr / 128x64 tile (1 m-frag per warp) -> 16 warps/SM
//  - mlp1T: 256 thr / 128x128 tile -> 24 warps/SM, single wave (391 blocks)
//  - fp16-split m16n8k16 GEMMs (fp32-grade), fp16 gather aggr, fused pre
// ---------------------------------------------------------------------------

#define NMAX 50048
#define EMAX 800000
typedef unsigned long long u64;
typedef unsigned int u32;

__device__ int2     g_edge[EMAX];
__device__ int      g_ssrc[EMAX];
__device__ int      g_deg[NMAX];
__device__ int      g_off[NMAX];
__device__ int      g_cur[NMAX];
__device__ int      g_part[64];
__device__ int      g_scan_done;
__device__ unsigned g_zh [NMAX * 32];     // half2 per entry (64 feats / row)
__device__ float    g_h  [NMAX * 64];
__device__ float    g_s  [NMAX * 64];
__device__ float    g_hid[NMAX * 128];

__device__ __forceinline__ float ex2f(float x) {
    float r; asm("ex2.approx.f32 %0, %1;" : "=f"(r) : "f"(x)); return r;
}
__device__ __forceinline__ unsigned h2pack(float a, float b) {
    __half2 h = __floats2half2_rn(a, b);
    return *(unsigned*)&h;
}
__device__ __forceinline__ float2 h2unpack(unsigned u) {
    __half2 h = *(__half2*)&u;
    return __half22float2(h);
}
// split a pair of floats into fp16 hi + fp16 lo packs
__device__ __forceinline__ void hsplit(float a, float b, u32 &hi, u32 &lo) {
    hi = h2pack(a, b);
    float2 f = h2unpack(hi);
    lo = h2pack(a - f.x, b - f.y);
}
__device__ __forceinline__ void mmah(float* d, const u32* a, u32 b0, u32 b1) {
    asm volatile(
        "mma.sync.aligned.m16n8k16.row.col.f32.f16.f16.f32 "
        "{%0,%1,%2,%3}, {%4,%5,%6,%7}, {%8,%9}, {%0,%1,%2,%3};"
        : "+f"(d[0]), "+f"(d[1]), "+f"(d[2]), "+f"(d[3])
        : "r"(a[0]), "r"(a[1]), "r"(a[2]), "r"(a[3]), "r"(b0), "r"(b1));
}

// ---------------------------------------------------------------------------
// Edge preprocessing (unchanged from round 8)
// ---------------------------------------------------------------------------
__global__ void k_normcount(const void* __restrict__ raw, int E) {
    __shared__ int s_is64;
    int tid = threadIdx.x;
    if (tid < 32) {
        const int* w = (const int*)raw;
        int bad = 0;
        int lim = min(128, E);
        for (int i = tid; i < lim; i += 32) bad |= w[2 * i + 1];
        unsigned b = __ballot_sync(0xffffffffu, bad != 0);
        if (tid == 0) s_is64 = (b == 0) ? 1 : 0;
    }
    if (blockIdx.x == 0 && tid == 0) g_scan_done = 0;
    __syncthreads();
    int is64 = s_is64;
    int base = (blockIdx.x * blockDim.x + tid) * 4;
    if (base >= E) return;
    if (is64) {
        const long long* p = (const long long*)raw;
        #pragma unroll
        for (int j = 0; j < 4; j++) {
            int e = base + j;
            if (e < E) {
                int s = (int)p[e], d = (int)p[(size_t)E + e];
                g_edge[e] = make_int2(s, d);
                atomicAdd(&g_deg[d], 1);
            }
        }
    } else {
        const int* p = (const int*)raw;
        #pragma unroll
        for (int j = 0; j < 4; j++) {
            int e = base + j;
            if (e < E) {
                int s = p[e], d = p[(size_t)E + e];
                g_edge[e] = make_int2(s, d);
                atomicAdd(&g_deg[d], 1);
            }
        }
    }
}

__global__ void k_scan(int n) {
    __shared__ int wsum[32];
    __shared__ int amLast;
    __shared__ int pp[64];
    int tid = threadIdx.x;
    int i = blockIdx.x * 1024 + tid;
    int v = (i < n) ? g_deg[i] : 0;
    int lane = tid & 31, wid = tid >> 5;
    int s = v;
    #pragma unroll
    for (int o = 1; o < 32; o <<= 1) {
        int t = __shfl_up_sync(0xffffffffu, s, o);
        if (lane >= o) s += t;
    }
    if (lane == 31) wsum[wid] = s;
    __syncthreads();
    if (wid == 0) {
        int w = wsum[lane];
        #pragma unroll
        for (int o = 1; o < 32; o <<= 1) {
            int t = __shfl_up_sync(0xffffffffu, w, o);
            if (lane >= o) w += t;
        }
        wsum[lane] = w;
    }
    __syncthreads();
    int base = wid ? wsum[wid - 1] : 0;
    int excl = base + s - v;
    if (i < n) { g_off[i] = excl; g_cur[i] = excl; }
    if (tid == 1023) {
        g_part[blockIdx.x] = base + s;
        __threadfence();
        int t = atomicAdd(&g_scan_done, 1);
        amLast = (t == (int)gridDim.x - 1);
    }
    __syncthreads();
    if (amLast) {
        int P = gridDim.x;
        if (tid < 64) pp[tid] = (tid < P) ? g_part[tid] : 0;
        __syncthreads();
        if (tid == 0) {
            int acc = 0;
            for (int k = 0; k < P; k++) { int vv = pp[k]; pp[k] = acc; acc += vv; }
        }
        __syncthreads();
        if (tid < P) g_part[tid] = pp[tid];
    }
}

__global__ void k_scatter(int E) {
    int base = (blockIdx.x * blockDim.x + threadIdx.x) * 4;
    if (base >= E) return;
    #pragma unroll
    for (int j = 0; j < 4; j++) {
        int e = base + j;
        if (e < E) {
            int2 ed = g_edge[e];
            int pos = atomicAdd(&g_cur[ed.y], 1) + g_part[ed.y >> 10];
            g_ssrc[pos] = ed.x;
        }
    }
}

// ---------------------------------------------------------------------------
// Softmax aggregation, warp per destination node, fp16 gather (unchanged)
// ---------------------------------------------------------------------------
__global__ void k_aggr(const float* __restrict__ tp, int li,
                       float* __restrict__ so, int N) {
    int w = (blockIdx.x * blockDim.x + threadIdx.x) >> 5;
    int lane = threadIdx.x & 31;
    if (w >= N) return;
    float tl = __ldg(tp + li) * 1.4426950408889634f;
    int beg = g_off[w] + g_part[w >> 10];
    int dg = g_deg[w];
    float se0 = 0.f, se1 = 0.f, sn0 = 0.f, sn1 = 0.f;
    #pragma unroll 4
    for (int j = 0; j < dg; j++) {
        int s = __ldg(&g_ssrc[beg + j]);
        float2 v = h2unpack(__ldg(&g_zh[(size_t)s * 32 + lane]));
        float m0 = fmaxf(v.x, 0.f);
        float m1 = fmaxf(v.y, 0.f);
        float e0 = ex2f(m0 * tl);
        float e1 = ex2f(m1 * tl);
        se0 += e0; se1 += e1;
        sn0 = fmaf(m0, e0, sn0);
        sn1 = fmaf(m1, e1, sn1);
    }
    float2 zd = h2unpack(g_zh[(size_t)w * 32 + lane]);
    float2 o;
    o.x = zd.x + fmaf(1e-7f, se0, sn0) / (se0 + 1e-16f);
    o.y = zd.y + fmaf(1e-7f, se1, sn1) / (se1 + 1e-16f);
    ((float2*)so)[(size_t)w * 32 + lane] = o;
}

// ---------------------------------------------------------------------------
// gemmT: [N,128] @ [128,64] + bias (+residual, +LN epilogue, +head)
// fp16-split m16n8k16. 256 thr / 8 warps; tile 128 rows x 64 cols;
// warp w: rows [w*16, w*16+16) (1 m-frag), 8 n-frags, 8 k-steps of 16.
// modes: 0 encoder -> zh only; 1 -> h fp32 + zh = relu(LN); 2 -> out + head
// ---------------------------------------------------------------------------
#define GEMMT_U32 (2 * 128 * 68 + 2 * 4096 + 400)
#define GEMMT_SMEM (GEMMT_U32 * 4)
__global__ __launch_bounds__(256) void k_gemmT(
    const float* __restrict__ A, const float* __restrict__ W,
    const float* __restrict__ bias, const float* __restrict__ lg,
    const float* __restrict__ lb, const float* __restrict__ lw,
    const float* __restrict__ lhb, float* __restrict__ h_out,
    float* __restrict__ z_out, int N, int addres, int mode) {
    extern __shared__ u32 smu[];
    u32*   Ah  = smu;                       // 128*68
    u32*   Al  = Ah + 128 * 68;             // 128*68
    uint2* Bh  = (uint2*)(Al + 128 * 68);   // 2048 uint2
    uint2* Bl  = Bh + 2048;                 // 2048 uint2
    float* bs  = (float*)(Bl + 2048);       // 64
    float* gs  = bs + 64;
    float* bb  = gs + 64;
    float* lws = bb + 64;                   // 208 (192 used)
    int tid = threadIdx.x;
    int r0 = blockIdx.x * 128;
    // stage A: hi/lo fp16 pairs, row-major kpairs, stride 68
    {
        const float4* a4 = (const float4*)A;
        #pragma unroll
        for (int i = 0; i < 16; i++) {
            int idx = tid + i * 256;                // 128 rows x 32 f4
            int row = idx >> 5, c = idx & 31;
            int grow = min(r0 + row, N - 1);
            float4 v = __ldg(&a4[(size_t)grow * 32 + c]);
            u32 h0, l0, h1, l1;
            hsplit(v.x, v.y, h0, l0);
            hsplit(v.z, v.w, h1, l1);
            *(uint2*)&Ah[row * 68 + 2 * c] = make_uint2(h0, h1);
            *(uint2*)&Al[row * 68 + 2 * c] = make_uint2(l0, l1);
        }
    }
    // stage B fragments: id = (ks*8+nf)*32 + lane
    {
        #pragma unroll
        for (int i = 0; i < 8; i++) {
            int id = tid + i * 256;                 // 0..2047
            int ln = id & 31, nf = (id >> 5) & 7, ks = id >> 8;
            int g = ln >> 2, t = ln & 3;
            int n = nf * 8 + g, k0 = ks * 16 + 2 * t;
            float w00 = __ldg(&W[(k0)     * 64 + n]);
            float w01 = __ldg(&W[(k0 + 1) * 64 + n]);
            float w10 = __ldg(&W[(k0 + 8) * 64 + n]);
            float w11 = __ldg(&W[(k0 + 9) * 64 + n]);
            u32 bh0, bl0, bh1, bl1;
            hsplit(w00, w01, bh0, bl0);
            hsplit(w10, w11, bh1, bl1);
            Bh[id] = make_uint2(bh0, bh1);
            Bl[id] = make_uint2(bl0, bl1);
        }
        if (tid < 64) {
            bs[tid] = bias[tid];
            if (mode) { gs[tid] = lg[tid]; bb[tid] = lb[tid]; }
        }
        if (mode == 2 && tid >= 64 && tid < 112)
            ((float4*)lws)[tid - 64] = ((const float4*)lw)[tid - 64];
    }
    __syncthreads();
    int warp = tid >> 5, lane = tid & 31;
    int g = lane >> 2, t = lane & 3;
    int wm = warp * 16;
    float acc[8][4];
    #pragma unroll
    for (int nf = 0; nf < 8; nf++)
        #pragma unroll
        for (int c = 0; c < 4; c++) acc[nf][c] = 0.f;
    int b0 = (wm + g) * 68, b1 = (wm + 8 + g) * 68;
    #pragma unroll
    for (int ks = 0; ks < 8; ks++) {
        int kp = ks * 8 + t;
        u32 ah[4], al[4];
        ah[0] = Ah[b0 + kp];     ah[1] = Ah[b1 + kp];
        ah[2] = Ah[b0 + kp + 4]; ah[3] = Ah[b1 + kp + 4];
        al[0] = Al[b0 + kp];     al[1] = Al[b1 + kp];
        al[2] = Al[b0 + kp + 4]; al[3] = Al[b1 + kp + 4];
        #pragma unroll
        for (int nf = 0; nf < 8; nf++) {
            uint2 bh = Bh[(ks * 8 + nf) * 32 + lane];
            uint2 bl = Bl[(ks * 8 + nf) * 32 + lane];
            mmah(acc[nf], ah, bl.x, bl.y);   // Ahi*Blo
            mmah(acc[nf], al, bh.x, bh.y);   // Alo*Bhi
            mmah(acc[nf], ah, bh.x, bh.y);   // Ahi*Bhi
        }
    }
    // epilogue: thread owns rows {wm+g, wm+8+g}, cols {8nf+2t, +1}
    #pragma unroll
    for (int rs = 0; rs < 2; rs++) {
        int rr = r0 + wm + g + rs * 8;
        bool ok = rr < N;
        float y[16];
        #pragma unroll
        for (int nf = 0; nf < 8; nf++) {
            float2 bv = *(float2*)&bs[8 * nf + 2 * t];
            y[2 * nf]     = acc[nf][rs * 2]     + bv.x;
            y[2 * nf + 1] = acc[nf][rs * 2 + 1] + bv.y;
        }
        if (addres && ok) {
            #pragma unroll
            for (int nf = 0; nf < 8; nf++) {
                float2 h = ((const float2*)h_out)[(size_t)rr * 32 + 4 * nf + t];
                y[2 * nf] += h.x; y[2 * nf + 1] += h.y;
            }
        }
        if (mode == 0) {
            if (ok) {
                #pragma unroll
                for (int nf = 0; nf < 8; nf++)
                    g_zh[(size_t)rr * 32 + 4 * nf + t] = h2pack(y[2 * nf], y[2 * nf + 1]);
            }
            continue;
        }
        if (mode == 1 && ok) {
            #pragma unroll
            for (int nf = 0; nf < 8; nf++) {
                float2 v; v.x = y[2 * nf]; v.y = y[2 * nf + 1];
                ((float2*)h_out)[(size_t)rr * 32 + 4 * nf + t] = v;
            }
        }
        float s = 0.f, q = 0.f;
        #pragma unroll
        for (int c = 0; c < 16; c++) { s += y[c]; q = fmaf(y[c], y[c], q); }
        s += __shfl_xor_sync(0xffffffffu, s, 1);
        q += __shfl_xor_sync(0xffffffffu, q, 1);
        s += __shfl_xor_sync(0xffffffffu, s, 2);
        q += __shfl_xor_sync(0xffffffffu, q, 2);
        float mu = s * (1.f / 64.f);
        float var = q * (1.f / 64.f) - mu * mu;
        float rsv = rsqrtf(var + 1e-5f);
        float o16[16];
        #pragma unroll
        for (int nf = 0; nf < 8; nf++) {
            float2 gv = *(float2*)&gs[8 * nf + 2 * t];
            float2 cv = *(float2*)&bb[8 * nf + 2 * t];
            o16[2 * nf]     = fmaxf((y[2 * nf]     - mu) * rsv * gv.x + cv.x, 0.f);
            o16[2 * nf + 1] = fmaxf((y[2 * nf + 1] - mu) * rsv * gv.y + cv.y, 0.f);
        }
        if (mode == 1) {
            if (ok) {
                #pragma unroll
                for (int nf = 0; nf < 8; nf++)
                    g_zh[(size_t)rr * 32 + 4 * nf + t] = h2pack(o16[2 * nf], o16[2 * nf + 1]);
            }
        } else {  // mode 2: final out + head
            if (ok) {
                #pragma unroll
                for (int nf = 0; nf < 8; nf++) {
                    float2 v; v.x = o16[2 * nf]; v.y = o16[2 * nf + 1];
                    ((float2*)z_out)[(size_t)rr * 32 + 4 * nf + t] = v;
                }
            }
            float p0 = 0.f, p1 = 0.f, p2 = 0.f;
            #pragma unroll
            for (int nf = 0; nf < 8; nf++) {
                int c0 = 8 * nf + 2 * t, c1 = c0 + 1;
                p0 = fmaf(o16[2 * nf], lws[c0 * 3 + 0], p0);
                p1 = fmaf(o16[2 * nf], lws[c0 * 3 + 1], p1);
                p2 = fmaf(o16[2 * nf], lws[c0 * 3 + 2], p2);
                p0 = fmaf(o16[2 * nf + 1], lws[c1 * 3 + 0], p0);
                p1 = fmaf(o16[2 * nf + 1], lws[c1 * 3 + 1], p1);
                p2 = fmaf(o16[2 * nf + 1], lws[c1 * 3 + 2], p2);
            }
            p0 += __shfl_xor_sync(0xffffffffu, p0, 1);
            p1 += __shfl_xor_sync(0xffffffffu, p1, 1);
            p2 += __shfl_xor_sync(0xffffffffu, p2, 1);
            p0 += __shfl_xor_sync(0xffffffffu, p0, 2);
            p1 += __shfl_xor_sync(0xffffffffu, p1, 2);
            p2 += __shfl_xor_sync(0xffffffffu, p2, 2);
            if (t == 0 && ok) {
                size_t base = (size_t)N * 64 + (size_t)rr * 3;
                z_out[base + 0] = p0 + __ldg(lhb + 0);
                z_out[base + 1] = p1 + __ldg(lhb + 1);
                z_out[base + 2] = p2 + __ldg(lhb + 2);
            }
        }
    }
}

// ---------------------------------------------------------------------------
// mlp1T: [N,64] @ [64,128] + bias -> LN(128) -> ReLU   fp16-split m16n8k16
// 256 thr / 8 warps; tile 128 rows x 128 cols; warp: 1 m-frag, 16 nf, 4 ks
// A hi/lo [128][36]; B frags [4ks][16nf][32lane] uint2 hi/lo
// ---------------------------------------------------------------------------
#define MLP1T_U32 (2 * 128 * 36 + 2 * 4096 + 384)
#define MLP1T_SMEM (MLP1T_U32 * 4)
__global__ __launch_bounds__(256) void k_mlp1T(
    const float* __restrict__ A, const float* __restrict__ W,
    const float* __restrict__ bias, const float* __restrict__ lg,
    const float* __restrict__ lb, float* __restrict__ out, int N) {
    extern __shared__ u32 smu[];
    u32*   Ah = smu;                        // 128*36
    u32*   Al = Ah + 128 * 36;
    uint2* Bh = (uint2*)(Al + 128 * 36);    // 2048 uint2
    uint2* Bl = Bh + 2048;
    float* bs = (float*)(Bl + 2048);        // 128
    float* gs = bs + 128;
    float* bb = gs + 128;
    int tid = threadIdx.x;
    int r0 = blockIdx.x * 128;
    {
        const float4* a4 = (const float4*)A;
        #pragma unroll
        for (int i = 0; i < 8; i++) {
            int idx = tid + i * 256;                // 128 rows x 16 f4
            int row = idx >> 4, c = idx & 15;
            int grow = min(r0 + row, N - 1);
            float4 v = __ldg(&a4[(size_t)grow * 16 + c]);
            u32 h0, l0, h1, l1;
            hsplit(v.x, v.y, h0, l0);
            hsplit(v.z, v.w, h1, l1);
            *(uint2*)&Ah[row * 36 + 2 * c] = make_uint2(h0, h1);
            *(uint2*)&Al[row * 36 + 2 * c] = make_uint2(l0, l1);
        }
        #pragma unroll
        for (int i = 0; i < 8; i++) {
            int id = tid + i * 256;                 // 0..2047
            int ln = id & 31, nf = (id >> 5) & 15, ks = id >> 9;
            int g = ln >> 2, t = ln & 3;
            int n = nf * 8 + g, k0 = ks * 16 + 2 * t;
            float w00 = __ldg(&W[(k0)     * 128 + n]);
            float w01 = __ldg(&W[(k0 + 1) * 128 + n]);
            float w10 = __ldg(&W[(k0 + 8) * 128 + n]);
            float w11 = __ldg(&W[(k0 + 9) * 128 + n]);
            u32 bh0, bl0, bh1, bl1;
            hsplit(w00, w01, bh0, bl0);
            hsplit(w10, w11, bh1, bl1);
            Bh[id] = make_uint2(bh0, bh1);
            Bl[id] = make_uint2(bl0, bl1);
        }
        if (tid < 128) { bs[tid] = bias[tid]; gs[tid] = lg[tid]; bb[tid] = lb[tid]; }
    }
    __syncthreads();
    int warp = tid >> 5, lane = tid & 31;
    int g = lane >> 2, t = lane & 3;
    int wm = warp * 16;
    float acc[16][4];
    #pragma unroll
    for (int nf = 0; nf < 16; nf++)
        #pragma unroll
        for (int c = 0; c < 4; c++) acc[nf][c] = 0.f;
    int b0 = (wm + g) * 36, b1 = (wm + 8 + g) * 36;
    #pragma unroll
    for (int ks = 0; ks < 4; ks++) {
        int kp = ks * 8 + t;
        u32 ah[4], al[4];
        ah[0] = Ah[b0 + kp];     ah[1] = Ah[b1 + kp];
        ah[2] = Ah[b0 + kp + 4]; ah[3] = Ah[b1 + kp + 4];
        al[0] = Al[b0 + kp];     al[1] = Al[b1 + kp];
        al[2] = Al[b0 + kp + 4]; al[3] = Al[b1 + kp + 4];
        #pragma unroll
        for (int nf = 0; nf < 16; nf++) {
            uint2 bh = Bh[(ks * 16 + nf) * 32 + lane];
            uint2 bl = Bl[(ks * 16 + nf) * 32 + lane];
            mmah(acc[nf], ah, bl.x, bl.y);
            mmah(acc[nf], al, bh.x, bh.y);
            mmah(acc[nf], ah, bh.x, bh.y);
        }
    }
    #pragma unroll
    for (int rs = 0; rs < 2; rs++) {
        int rr = r0 + wm + g + rs * 8;
        float y[32];
        #pragma unroll
        for (int nf = 0; nf < 16; nf++) {
            float2 bv = *(float2*)&bs[8 * nf + 2 * t];
            y[2 * nf]     = acc[nf][rs * 2]     + bv.x;
            y[2 * nf + 1] = acc[nf][rs * 2 + 1] + bv.y;
        }
        float s = 0.f, q = 0.f;
        #pragma unroll
        for (int c = 0; c < 32; c++) { s += y[c]; q = fmaf(y[c], y[c], q); }
        s += __shfl_xor_sync(0xffffffffu, s, 1);
        q += __shfl_xor_sync(0xffffffffu, q, 1);
        s += __shfl_xor_sync(0xffffffffu, s, 2);
        q += __shfl_xor_sync(0xffffffffu, q, 2);
        float mu = s * (1.f / 128.f);
        float var = q * (1.f / 128.f) - mu * mu;
        float rsv = rsqrtf(var + 1e-5f);
        if (rr < N) {
            #pragma unroll
            for (int nf = 0; nf < 16; nf++) {
                float2 gv = *(float2*)&gs[8 * nf + 2 * t];
                float2 cv = *(float2*)&bb[8 * nf + 2 * t];
                float2 v;
                v.x = fmaxf((y[2 * nf]     - mu) * rsv * gv.x + cv.x, 0.f);
                v.y = fmaxf((y[2 * nf + 1] - mu) * rsv * gv.y + cv.y, 0.f);
                ((float2*)out)[(size_t)rr * 64 + 4 * nf + t] = v;
            }
        }
    }
}

// ---------------------------------------------------------------------------
// Host launch
// ---------------------------------------------------------------------------
extern "C" void kernel_launch(void* const* d_in, const int* in_sizes, int n_in,
                              void* d_out, int out_size) {
    const float* x    = (const float*)d_in[0];
    const void*  ei   = d_in[1];
    const float* encW = (const float*)d_in[2];
    const float* encB = (const float*)d_in[3];
    const float* t    = (const float*)d_in[4];
    const float* W1   = (const float*)d_in[5];
    const float* b1   = (const float*)d_in[6];
    const float* g1   = (const float*)d_in[7];
    const float* bb1  = (const float*)d_in[8];
    const float* W2   = (const float*)d_in[9];
    const float* b2   = (const float*)d_in[10];
    const float* ng   = (const float*)d_in[11];
    const float* nb   = (const float*)d_in[12];
    const float* lw   = (const float*)d_in[13];
    const float* lb   = (const float*)d_in[14];
    int N = in_sizes[0] / 128;
    int E = in_sizes[1] / 2;
    if (N > NMAX) N = NMAX;
    if (E > EMAX) E = EMAX;
    float* out = (float*)d_out;

    cudaFuncSetAttribute(k_mlp1T, cudaFuncAttributeMaxDynamicSharedMemorySize, MLP1T_SMEM);
    cudaFuncSetAttribute(k_gemmT, cudaFuncAttributeMaxDynamicSharedMemorySize, GEMMT_SMEM);

    float *gh, *gsv, *ghid;
    int *gdeg;
    cudaGetSymbolAddress((void**)&gh,   g_h);
    cudaGetSymbolAddress((void**)&gsv,  g_s);
    cudaGetSymbolAddress((void**)&ghid, g_hid);
    cudaGetSymbolAddress((void**)&gdeg, g_deg);

    int eb4     = (E + 1023) / 1024;
    int rowsW   = (N + 7) / 8;
    int tilesB  = (N + 127) / 128;
    int sblocks = (N + 1023) / 1024;

    // edge preprocessing (CSR by dst)
    cudaMemsetAsync(gdeg, 0, (size_t)N * sizeof(int));
    k_normcount<<<eb4, 256>>>(ei, E);
    k_scan<<<sblocks, 1024>>>(N);
    k_scatter<<<eb4, 256>>>(E);

    // encoder: x @ encW + encB -> zh (mode 0)
    k_gemmT<<<tilesB, 256, GEMMT_SMEM>>>(x, encW, encB, nullptr, nullptr,
                                         nullptr, nullptr, gh, nullptr, N, 0, 0);

    for (int i = 0; i < 3; i++) {
        k_aggr<<<rowsW, 256>>>(t, i, gsv, N);
        k_mlp1T<<<tilesB, 256, MLP1T_SMEM>>>(gsv, W1 + i * 8192, b1 + i * 128,
                                             g1 + i * 128, bb1 + i * 128, ghid, N);
        if (i < 2) {
            // mlp2 (+res if i>0) -> gh fp32; zh = relu(LN(gh, ng[i+1]))
            k_gemmT<<<tilesB, 256, GEMMT_SMEM>>>(ghid, W2 + i * 8192, b2 + i * 64,
                                                 ng + (i + 1) * 64, nb + (i + 1) * 64,
                                                 nullptr, nullptr, gh, nullptr,
                                                 N, i ? 1 : 0, 1);
        } else {
            // last: res + final LN(ng[0]) + ReLU -> out, head -> out tail
            k_gemmT<<<tilesB, 256, GEMMT_SMEM>>>(ghid, W2 + i * 8192, b2 + i * 64,
                                                 ng, nb, lw, lb, gh, out, N, 1, 2);
        }
    }
}

// round 12
// speedup vs baseline: 2.1420x; 1.0328x over previous
#include <cuda_runtime.h>
#include <cuda_fp16.h>

// ---------------------------------------------------------------------------
// DeeperGCN round 12 (round-10/11 resubmit after repeated infra failures):
//  - weight fragments pre-packed ONCE per replay (k_pack, 7 blocks) ->
//    GEMM B staging becomes 8 coalesced uint4 loads/thread (was 32 scattered
//    4B LDGs/thread re-reading the same 32KB every block = the r9 bottleneck)
//  - fp16-split m16n8k16 GEMMs, fp16 gather aggregation, fused preprocessing
// ---------------------------------------------------------------------------

#define NMAX 50048
#define EMAX 800000
typedef unsigned long long u64;
typedef unsigned int u32;

__device__ int2     g_edge[EMAX];
__device__ int      g_ssrc[EMAX];
__device__ int      g_deg[NMAX];
__device__ int      g_off[NMAX];
__device__ int      g_cur[NMAX];
__device__ int      g_part[64];
__device__ int      g_scan_done;
__device__ unsigned g_zh [NMAX * 32];     // half2 per entry (64 feats / row)
__device__ float    g_h  [NMAX * 64];
__device__ float    g_s  [NMAX * 64];
__device__ float    g_hid[NMAX * 128];
// pre-packed weight fragments: mats 0=enc, 1..3=W2_i (gemm type), 4..6=W1_i (mlp)
__device__ uint2    g_bph[7][2048];
__device__ uint2    g_bpl[7][2048];

__device__ __forceinline__ float ex2f(float x) {
    float r; asm("ex2.approx.f32 %0, %1;" : "=f"(r) : "f"(x)); return r;
}
__device__ __forceinline__ unsigned h2pack(float a, float b) {
    __half2 h = __floats2half2_rn(a, b);
    return *(unsigned*)&h;
}
__device__ __forceinline__ float2 h2unpack(unsigned u) {
    __half2 h = *(__half2*)&u;
    return __half22float2(h);
}
__device__ __forceinline__ void hsplit(float a, float b, u32 &hi, u32 &lo) {
    hi = h2pack(a, b);
    float2 f = h2unpack(hi);
    lo = h2pack(a - f.x, b - f.y);
}
__device__ __forceinline__ void mmah(float* d, const u32* a, u32 b0, u32 b1) {
    asm volatile(
        "mma.sync.aligned.m16n8k16.row.col.f32.f16.f16.f32 "
        "{%0,%1,%2,%3}, {%4,%5,%6,%7}, {%8,%9}, {%0,%1,%2,%3};"
        : "+f"(d[0]), "+f"(d[1]), "+f"(d[2]), "+f"(d[3])
        : "r"(a[0]), "r"(a[1]), "r"(a[2]), "r"(a[3]), "r"(b0), "r"(b1));
}

// ---------------------------------------------------------------------------
// k_pack: one-time fragment packing of all 7 weight matrices (32KB each)
// ---------------------------------------------------------------------------
__global__ __launch_bounds__(256) void k_pack(const float* __restrict__ encW,
                                              const float* __restrict__ W1,
                                              const float* __restrict__ W2) {
    __shared__ float sw[8192];
    int b = blockIdx.x;  // 0: enc, 1..3: W2_i, 4..6: W1_i
    const float* src = (b == 0) ? encW : (b < 4 ? W2 + (b - 1) * 8192
                                                : W1 + (b - 4) * 8192);
    int tid = threadIdx.x;
    const float4* s4 = (const float4*)src;
    #pragma unroll
    for (int i = 0; i < 8; i++)
        ((float4*)sw)[tid + i * 256] = __ldg(&s4[tid + i * 256]);
    __syncthreads();
    bool mlp = (b >= 4);
    #pragma unroll
    for (int i = 0; i < 8; i++) {
        int id = tid + i * 256;                 // 0..2047
        int ln = id & 31;
        int g = ln >> 2, t = ln & 3;
        int nf, ks, stride;
        if (!mlp) { nf = (id >> 5) & 7;  ks = id >> 8; stride = 64; }
        else      { nf = (id >> 5) & 15; ks = id >> 9; stride = 128; }
        int n = nf * 8 + g, k0 = ks * 16 + 2 * t;
        float w00 = sw[(k0)     * stride + n];
        float w01 = sw[(k0 + 1) * stride + n];
        float w10 = sw[(k0 + 8) * stride + n];
        float w11 = sw[(k0 + 9) * stride + n];
        u32 bh0, bl0, bh1, bl1;
        hsplit(w00, w01, bh0, bl0);
        hsplit(w10, w11, bh1, bl1);
        g_bph[b][id] = make_uint2(bh0, bh1);
        g_bpl[b][id] = make_uint2(bl0, bl1);
    }
}

// ---------------------------------------------------------------------------
// Edge preprocessing (unchanged)
// ---------------------------------------------------------------------------
__global__ void k_normcount(const void* __restrict__ raw, int E) {
    __shared__ int s_is64;
    int tid = threadIdx.x;
    if (tid < 32) {
        const int* w = (const int*)raw;
        int bad = 0;
        int lim = min(128, E);
        for (int i = tid; i < lim; i += 32) bad |= w[2 * i + 1];
        unsigned b = __ballot_sync(0xffffffffu, bad != 0);
        if (tid == 0) s_is64 = (b == 0) ? 1 : 0;
    }
    if (blockIdx.x == 0 && tid == 0) g_scan_done = 0;
    __syncthreads();
    int is64 = s_is64;
    int base = (blockIdx.x * blockDim.x + tid) * 4;
    if (base >= E) return;
    if (is64) {
        const long long* p = (const long long*)raw;
        #pragma unroll
        for (int j = 0; j < 4; j++) {
            int e = base + j;
            if (e < E) {
                int s = (int)p[e], d = (int)p[(size_t)E + e];
                g_edge[e] = make_int2(s, d);
                atomicAdd(&g_deg[d], 1);
            }
        }
    } else {
        const int* p = (const int*)raw;
        #pragma unroll
        for (int j = 0; j < 4; j++) {
            int e = base + j;
            if (e < E) {
                int s = p[e], d = p[(size_t)E + e];
                g_edge[e] = make_int2(s, d);
                atomicAdd(&g_deg[d], 1);
            }
        }
    }
}

__global__ void k_scan(int n) {
    __shared__ int wsum[32];
    __shared__ int amLast;
    __shared__ int pp[64];
    int tid = threadIdx.x;
    int i = blockIdx.x * 1024 + tid;
    int v = (i < n) ? g_deg[i] : 0;
    int lane = tid & 31, wid = tid >> 5;
    int s = v;
    #pragma unroll
    for (int o = 1; o < 32; o <<= 1) {
        int t = __shfl_up_sync(0xffffffffu, s, o);
        if (lane >= o) s += t;
    }
    if (lane == 31) wsum[wid] = s;
    __syncthreads();
    if (wid == 0) {
        int w = wsum[lane];
        #pragma unroll
        for (int o = 1; o < 32; o <<= 1) {
            int t = __shfl_up_sync(0xffffffffu, w, o);
            if (lane >= o) w += t;
        }
        wsum[lane] = w;
    }
    __syncthreads();
    int base = wid ? wsum[wid - 1] : 0;
    int excl = base + s - v;
    if (i < n) { g_off[i] = excl; g_cur[i] = excl; }
    if (tid == 1023) {
        g_part[blockIdx.x] = base + s;
        __threadfence();
        int t = atomicAdd(&g_scan_done, 1);
        amLast = (t == (int)gridDim.x - 1);
    }
    __syncthreads();
    if (amLast) {
        int P = gridDim.x;
        if (tid < 64) pp[tid] = (tid < P) ? g_part[tid] : 0;
        __syncthreads();
        if (tid == 0) {
            int acc = 0;
            for (int k = 0; k < P; k++) { int vv = pp[k]; pp[k] = acc; acc += vv; }
        }
        __syncthreads();
        if (tid < P) g_part[tid] = pp[tid];
    }
}

__global__ void k_scatter(int E) {
    int base = (blockIdx.x * blockDim.x + threadIdx.x) * 4;
    if (base >= E) return;
    #pragma unroll
    for (int j = 0; j < 4; j++) {
        int e = base + j;
        if (e < E) {
            int2 ed = g_edge[e];
            int pos = atomicAdd(&g_cur[ed.y], 1) + g_part[ed.y >> 10];
            g_ssrc[pos] = ed.x;
        }
    }
}

// ---------------------------------------------------------------------------
// Softmax aggregation, warp per destination node, fp16 gather (unchanged)
// ---------------------------------------------------------------------------
__global__ void k_aggr(const float* __restrict__ tp, int li,
                       float* __restrict__ so, int N) {
    int w = (blockIdx.x * blockDim.x + threadIdx.x) >> 5;
    int lane = threadIdx.x & 31;
    if (w >= N) return;
    float tl = __ldg(tp + li) * 1.4426950408889634f;
    int beg = g_off[w] + g_part[w >> 10];
    int dg = g_deg[w];
    float se0 = 0.f, se1 = 0.f, sn0 = 0.f, sn1 = 0.f;
    #pragma unroll 4
    for (int j = 0; j < dg; j++) {
        int s = __ldg(&g_ssrc[beg + j]);
        float2 v = h2unpack(__ldg(&g_zh[(size_t)s * 32 + lane]));
        float m0 = fmaxf(v.x, 0.f);
        float m1 = fmaxf(v.y, 0.f);
        float e0 = ex2f(m0 * tl);
        float e1 = ex2f(m1 * tl);
        se0 += e0; se1 += e1;
        sn0 = fmaf(m0, e0, sn0);
        sn1 = fmaf(m1, e1, sn1);
    }
    float2 zd = h2unpack(g_zh[(size_t)w * 32 + lane]);
    float2 o;
    o.x = zd.x + fmaf(1e-7f, se0, sn0) / (se0 + 1e-16f);
    o.y = zd.y + fmaf(1e-7f, se1, sn1) / (se1 + 1e-16f);
    ((float2*)so)[(size_t)w * 32 + lane] = o;
}

// ---------------------------------------------------------------------------
// gemmT: [N,128] @ [128,64] + bias (+residual, +LN epilogue, +head)
// fp16-split m16n8k16. 256 thr / 8 warps; tile 128 x 64; B frags pre-packed.
// modes: 0 encoder -> zh only; 1 -> h fp32 + zh = relu(LN); 2 -> out + head
// ---------------------------------------------------------------------------
#define GEMMT_U32 (2 * 128 * 68 + 2 * 4096 + 400)
#define GEMMT_SMEM (GEMMT_U32 * 4)
__global__ __launch_bounds__(256) void k_gemmT(
    const float* __restrict__ A, int mat,
    const float* __restrict__ bias, const float* __restrict__ lg,
    const float* __restrict__ lb, const float* __restrict__ lw,
    const float* __restrict__ lhb, float* __restrict__ h_out,
    float* __restrict__ z_out, int N, int addres, int mode) {
    extern __shared__ u32 smu[];
    u32*   Ah  = smu;                       // 128*68
    u32*   Al  = Ah + 128 * 68;             // 128*68
    uint2* Bh  = (uint2*)(Al + 128 * 68);   // 2048 uint2
    uint2* Bl  = Bh + 2048;                 // 2048 uint2
    float* bs  = (float*)(Bl + 2048);       // 64
    float* gs  = bs + 64;
    float* bb  = gs + 64;
    float* lws = bb + 64;                   // 208 (192 used)
    int tid = threadIdx.x;
    int r0 = blockIdx.x * 128;
    // stage A: hi/lo fp16 pairs, row-major kpairs, stride 68
    {
        const float4* a4 = (const float4*)A;
        #pragma unroll
        for (int i = 0; i < 16; i++) {
            int idx = tid + i * 256;                // 128 rows x 32 f4
            int row = idx >> 5, c = idx & 31;
            int grow = min(r0 + row, N - 1);
            float4 v = __ldg(&a4[(size_t)grow * 32 + c]);
            u32 h0, l0, h1, l1;
            hsplit(v.x, v.y, h0, l0);
            hsplit(v.z, v.w, h1, l1);
            *(uint2*)&Ah[row * 68 + 2 * c] = make_uint2(h0, h1);
            *(uint2*)&Al[row * 68 + 2 * c] = make_uint2(l0, l1);
        }
    }
    // stage B: coalesced copy of pre-packed fragments
    {
        const uint4* ph = (const uint4*)g_bph[mat];
        const uint4* pl = (const uint4*)g_bpl[mat];
        uint4* dh = (uint4*)Bh;
        uint4* dl = (uint4*)Bl;
        #pragma unroll
        for (int i = 0; i < 4; i++) {
            dh[tid + i * 256] = __ldg(&ph[tid + i * 256]);
            dl[tid + i * 256] = __ldg(&pl[tid + i * 256]);
        }
        if (tid < 64) {
            bs[tid] = bias[tid];
            if (mode) { gs[tid] = lg[tid]; bb[tid] = lb[tid]; }
        }
        if (mode == 2 && tid >= 64 && tid < 112)
            ((float4*)lws)[tid - 64] = ((const float4*)lw)[tid - 64];
    }
    __syncthreads();
    int warp = tid >> 5, lane = tid & 31;
    int g = lane >> 2, t = lane & 3;
    int wm = warp * 16;
    float acc[8][4];
    #pragma unroll
    for (int nf = 0; nf < 8; nf++)
        #pragma unroll
        for (int c = 0; c < 4; c++) acc[nf][c] = 0.f;
    int b0 = (wm + g) * 68, b1 = (wm + 8 + g) * 68;
    #pragma unroll
    for (int ks = 0; ks < 8; ks++) {
        int kp = ks * 8 + t;
        u32 ah[4], al[4];
        ah[0] = Ah[b0 + kp];     ah[1] = Ah[b1 + kp];
        ah[2] = Ah[b0 + kp + 4]; ah[3] = Ah[b1 + kp + 4];
        al[0] = Al[b0 + kp];     al[1] = Al[b1 + kp];
        al[2] = Al[b0 + kp + 4]; al[3] = Al[b1 + kp + 4];
        #pragma unroll
        for (int nf = 0; nf < 8; nf++) {
            uint2 bh = Bh[(ks * 8 + nf) * 32 + lane];
            uint2 bl = Bl[(ks * 8 + nf) * 32 + lane];
            mmah(acc[nf], ah, bl.x, bl.y);   // Ahi*Blo
            mmah(acc[nf], al, bh.x, bh.y);   // Alo*Bhi
            mmah(acc[nf], ah, bh.x, bh.y);   // Ahi*Bhi
        }
    }
    // epilogue: thread owns rows {wm+g, wm+8+g}, cols {8nf+2t, +1}
    #pragma unroll
    for (int rs = 0; rs < 2; rs++) {
        int rr = r0 + wm + g + rs * 8;
        bool ok = rr < N;
        float y[16];
        #pragma unroll
        for (int nf = 0; nf < 8; nf++) {
            float2 bv = *(float2*)&bs[8 * nf + 2 * t];
            y[2 * nf]     = acc[nf][rs * 2]     + bv.x;
            y[2 * nf + 1] = acc[nf][rs * 2 + 1] + bv.y;
        }
        if (addres && ok) {
            #pragma unroll
            for (int nf = 0; nf < 8; nf++) {
                float2 h = ((const float2*)h_out)[(size_t)rr * 32 + 4 * nf + t];
                y[2 * nf] += h.x; y[2 * nf + 1] += h.y;
            }
        }
        if (mode == 0) {
            if (ok) {
                #pragma unroll
                for (int nf = 0; nf < 8; nf++)
                    g_zh[(size_t)rr * 32 + 4 * nf + t] = h2pack(y[2 * nf], y[2 * nf + 1]);
            }
            continue;
        }
        if (mode == 1 && ok) {
            #pragma unroll
            for (int nf = 0; nf < 8; nf++) {
                float2 v; v.x = y[2 * nf]; v.y = y[2 * nf + 1];
                ((float2*)h_out)[(size_t)rr * 32 + 4 * nf + t] = v;
            }
        }
        float s = 0.f, q = 0.f;
        #pragma unroll
        for (int c = 0; c < 16; c++) { s += y[c]; q = fmaf(y[c], y[c], q); }
        s += __shfl_xor_sync(0xffffffffu, s, 1);
        q += __shfl_xor_sync(0xffffffffu, q, 1);
        s += __shfl_xor_sync(0xffffffffu, s, 2);
        q += __shfl_xor_sync(0xffffffffu, q, 2);
        float mu = s * (1.f / 64.f);
        float var = q * (1.f / 64.f) - mu * mu;
        float rsv = rsqrtf(var + 1e-5f);
        float o16[16];
        #pragma unroll
        for (int nf = 0; nf < 8; nf++) {
            float2 gv = *(float2*)&gs[8 * nf + 2 * t];
            float2 cv = *(float2*)&bb[8 * nf + 2 * t];
            o16[2 * nf]     = fmaxf((y[2 * nf]     - mu) * rsv * gv.x + cv.x, 0.f);
            o16[2 * nf + 1] = fmaxf((y[2 * nf + 1] - mu) * rsv * gv.y + cv.y, 0.f);
        }
        if (mode == 1) {
            if (ok) {
                #pragma unroll
                for (int nf = 0; nf < 8; nf++)
                    g_zh[(size_t)rr * 32 + 4 * nf + t] = h2pack(o16[2 * nf], o16[2 * nf + 1]);
            }
        } else {  // mode 2: final out + head
            if (ok) {
                #pragma unroll
                for (int nf = 0; nf < 8; nf++) {
                    float2 v; v.x = o16[2 * nf]; v.y = o16[2 * nf + 1];
                    ((float2*)z_out)[(size_t)rr * 32 + 4 * nf + t] = v;
                }
            }
            float p0 = 0.f, p1 = 0.f, p2 = 0.f;
            #pragma unroll
            for (int nf = 0; nf < 8; nf++) {
                int c0 = 8 * nf + 2 * t, c1 = c0 + 1;
                p0 = fmaf(o16[2 * nf], lws[c0 * 3 + 0], p0);
                p1 = fmaf(o16[2 * nf], lws[c0 * 3 + 1], p1);
                p2 = fmaf(o16[2 * nf], lws[c0 * 3 + 2], p2);
                p0 = fmaf(o16[2 * nf + 1], lws[c1 * 3 + 0], p0);
                p1 = fmaf(o16[2 * nf + 1], lws[c1 * 3 + 1], p1);
                p2 = fmaf(o16[2 * nf + 1], lws[c1 * 3 + 2], p2);
            }
            p0 += __shfl_xor_sync(0xffffffffu, p0, 1);
            p1 += __shfl_xor_sync(0xffffffffu, p1, 1);
            p2 += __shfl_xor_sync(0xffffffffu, p2, 1);
            p0 += __shfl_xor_sync(0xffffffffu, p0, 2);
            p1 += __shfl_xor_sync(0xffffffffu, p1, 2);
            p2 += __shfl_xor_sync(0xffffffffu, p2, 2);
            if (t == 0 && ok) {
                size_t base = (size_t)N * 64 + (size_t)rr * 3;
                z_out[base + 0] = p0 + __ldg(lhb + 0);
                z_out[base + 1] = p1 + __ldg(lhb + 1);
                z_out[base + 2] = p2 + __ldg(lhb + 2);
            }
        }
    }
}

// ---------------------------------------------------------------------------
// mlp1T: [N,64] @ [64,128] + bias -> LN(128) -> ReLU   fp16-split m16n8k16
// 256 thr / 8 warps; tile 128 x 128; B frags pre-packed (mat index 4..6)
// ---------------------------------------------------------------------------
#define MLP1T_U32 (2 * 128 * 36 + 2 * 4096 + 384)
#define MLP1T_SMEM (MLP1T_U32 * 4)
__global__ __launch_bounds__(256) void k_mlp1T(
    const float* __restrict__ A, int mat,
    const float* __restrict__ bias, const float* __restrict__ lg,
    const float* __restrict__ lb, float* __restrict__ out, int N) {
    extern __shared__ u32 smu[];
    u32*   Ah = smu;                        // 128*36
    u32*   Al = Ah + 128 * 36;
    uint2* Bh = (uint2*)(Al + 128 * 36);    // 2048 uint2
    uint2* Bl = Bh + 2048;
    float* bs = (float*)(Bl + 2048);        // 128
    float* gs = bs + 128;
    float* bb = gs + 128;
    int tid = threadIdx.x;
    int r0 = blockIdx.x * 128;
    {
        const float4* a4 = (const float4*)A;
        #pragma unroll
        for (int i = 0; i < 8; i++) {
            int idx = tid + i * 256;                // 128 rows x 16 f4
            int row = idx >> 4, c = idx & 15;
            int grow = min(r0 + row, N - 1);
            float4 v = __ldg(&a4[(size_t)grow * 16 + c]);
            u32 h0, l0, h1, l1;
            hsplit(v.x, v.y, h0, l0);
            hsplit(v.z, v.w, h1, l1);
            *(uint2*)&Ah[row * 36 + 2 * c] = make_uint2(h0, h1);
            *(uint2*)&Al[row * 36 + 2 * c] = make_uint2(l0, l1);
        }
        const uint4* ph = (const uint4*)g_bph[mat];
        const uint4* pl = (const uint4*)g_bpl[mat];
        uint4* dh = (uint4*)Bh;
        uint4* dl = (uint4*)Bl;
        #pragma unroll
        for (int i = 0; i < 4; i++) {
            dh[tid + i * 256] = __ldg(&ph[tid + i * 256]);
            dl[tid + i * 256] = __ldg(&pl[tid + i * 256]);
        }
        if (tid < 128) { bs[tid] = bias[tid]; gs[tid] = lg[tid]; bb[tid] = lb[tid]; }
    }
    __syncthreads();
    int warp = tid >> 5, lane = tid & 31;
    int g = lane >> 2, t = lane & 3;
    int wm = warp * 16;
    float acc[16][4];
    #pragma unroll
    for (int nf = 0; nf < 16; nf++)
        #pragma unroll
        for (int c = 0; c < 4; c++) acc[nf][c] = 0.f;
    int b0 = (wm + g) * 36, b1 = (wm + 8 + g) * 36;
    #pragma unroll
    for (int ks = 0; ks < 4; ks++) {
        int kp = ks * 8 + t;
        u32 ah[4], al[4];
        ah[0] = Ah[b0 + kp];     ah[1] = Ah[b1 + kp];
        ah[2] = Ah[b0 + kp + 4]; ah[3] = Ah[b1 + kp + 4];
        al[0] = Al[b0 + kp];     al[1] = Al[b1 + kp];
        al[2] = Al[b0 + kp + 4]; al[3] = Al[b1 + kp + 4];
        #pragma unroll
        for (int nf = 0; nf < 16; nf++) {
            uint2 bh = Bh[(ks * 16 + nf) * 32 + lane];
            uint2 bl = Bl[(ks * 16 + nf) * 32 + lane];
            mmah(acc[nf], ah, bl.x, bl.y);
            mmah(acc[nf], al, bh.x, bh.y);
            mmah(acc[nf], ah, bh.x, bh.y);
        }
    }
    #pragma unroll
    for (int rs = 0; rs < 2; rs++) {
        int rr = r0 + wm + g + rs * 8;
        float y[32];
        #pragma unroll
        for (int nf = 0; nf < 16; nf++) {
            float2 bv = *(float2*)&bs[8 * nf + 2 * t];
            y[2 * nf]     = acc[nf][rs * 2]     + bv.x;
            y[2 * nf + 1] = acc[nf][rs * 2 + 1] + bv.y;
        }
        float s = 0.f, q = 0.f;
        #pragma unroll
        for (int c = 0; c < 32; c++) { s += y[c]; q = fmaf(y[c], y[c], q); }
        s += __shfl_xor_sync(0xffffffffu, s, 1);
        q += __shfl_xor_sync(0xffffffffu, q, 1);
        s += __shfl_xor_sync(0xffffffffu, s, 2);
        q += __shfl_xor_sync(0xffffffffu, q, 2);
        float mu = s * (1.f / 128.f);
        float var = q * (1.f / 128.f) - mu * mu;
        float rsv = rsqrtf(var + 1e-5f);
        if (rr < N) {
            #pragma unroll
            for (int nf = 0; nf < 16; nf++) {
                float2 gv = *(float2*)&gs[8 * nf + 2 * t];
                float2 cv = *(float2*)&bb[8 * nf + 2 * t];
                float2 v;
                v.x = fmaxf((y[2 * nf]     - mu) * rsv * gv.x + cv.x, 0.f);
                v.y = fmaxf((y[2 * nf + 1] - mu) * rsv * gv.y + cv.y, 0.f);
                ((float2*)out)[(size_t)rr * 64 + 4 * nf + t] = v;
            }
        }
    }
}

// ---------------------------------------------------------------------------
// Host launch
// ---------------------------------------------------------------------------
extern "C" void kernel_launch(void* const* d_in, const int* in_sizes, int n_in,
                              void* d_out, int out_size) {
    const float* x    = (const float*)d_in[0];
    const void*  ei   = d_in[1];
    const float* encW = (const float*)d_in[2];
    const float* encB = (const float*)d_in[3];
    const float* t    = (const float*)d_in[4];
    const float* W1   = (const float*)d_in[5];
    const float* b1   = (const float*)d_in[6];
    const float* g1   = (const float*)d_in[7];
    const float* bb1  = (const float*)d_in[8];
    const float* W2   = (const float*)d_in[9];
    const float* b2   = (const float*)d_in[10];
    const float* ng   = (const float*)d_in[11];
    const float* nb   = (const float*)d_in[12];
    const float* lw   = (const float*)d_in[13];
    const float* lb   = (const float*)d_in[14];
    int N = in_sizes[0] / 128;
    int E = in_sizes[1] / 2;
    if (N > NMAX) N = NMAX;
    if (E > EMAX) E = EMAX;
    float* out = (float*)d_out;

    cudaFuncSetAttribute(k_mlp1T, cudaFuncAttributeMaxDynamicSharedMemorySize, MLP1T_SMEM);
    cudaFuncSetAttribute(k_gemmT, cudaFuncAttributeMaxDynamicSharedMemorySize, GEMMT_SMEM);

    float *gh, *gsv, *ghid;
    int *gdeg;
    cudaGetSymbolAddress((void**)&gh,   g_h);
    cudaGetSymbolAddress((void**)&gsv,  g_s);
    cudaGetSymbolAddress((void**)&ghid, g_hid);
    cudaGetSymbolAddress((void**)&gdeg, g_deg);

    int eb4     = (E + 1023) / 1024;
    int rowsW   = (N + 7) / 8;
    int tilesB  = (N + 127) / 128;
    int sblocks = (N + 1023) / 1024;

    // edge preprocessing (CSR by dst)
    cudaMemsetAsync(gdeg, 0, (size_t)N * sizeof(int));
    k_normcount<<<eb4, 256>>>(ei, E);
    // one-time weight fragment packing (overlaps with scan/scatter)
    k_pack<<<7, 256>>>(encW, W1, W2);
    k_scan<<<sblocks, 1024>>>(N);
    k_scatter<<<eb4, 256>>>(E);

    // encoder: x @ encW + encB -> zh (mode 0, mat 0)
    k_gemmT<<<tilesB, 256, GEMMT_SMEM>>>(x, 0, encB, nullptr, nullptr,
                                         nullptr, nullptr, gh, nullptr, N, 0, 0);

    for (int i = 0; i < 3; i++) {
        k_aggr<<<rowsW, 256>>>(t, i, gsv, N);
        k_mlp1T<<<tilesB, 256, MLP1T_SMEM>>>(gsv, 4 + i, b1 + i * 128,
                                             g1 + i * 128, bb1 + i * 128, ghid, N);
        if (i < 2) {
            // mlp2 (+res if i>0) -> gh fp32; zh = relu(LN(gh, ng[i+1]))
            k_gemmT<<<tilesB, 256, GEMMT_SMEM>>>(ghid, 1 + i, b2 + i * 64,
                                                 ng + (i + 1) * 64, nb + (i + 1) * 64,
                                                 nullptr, nullptr, gh, nullptr,
                                                 N, i ? 1 : 0, 1);
        } else {
            // last: res + final LN(ng[0]) + ReLU -> out, head -> out tail
            k_gemmT<<<tilesB, 256, GEMMT_SMEM>>>(ghid, 1 + i, b2 + i * 64,
                                                 ng, nb, lw, lb, gh, out, N, 1, 2);
        }
    }
}